// round 1
// baseline (speedup 1.0000x reference)
#include <cuda_runtime.h>

#define N_VEH 16
#define N_PED 16
#define NTOK  32
#define DVEH  40
#define DPED  24
#define EDIM  128
#define NHEAD 4
#define DHEAD 32
#define OBSD  1056   // 16*40 + 16*24 + 32
#define XPAD  (EDIM + 4)

// Folded attention weight vectors: wa[layer][src0/dst1][k][head]
__device__ float g_wa[2][2][EDIM][NHEAD];

__global__ void fold_kernel(const float* __restrict__ w0,
                            const float* __restrict__ as0, const float* __restrict__ ad0,
                            const float* __restrict__ w1,
                            const float* __restrict__ as1, const float* __restrict__ ad1) {
    int idx = blockIdx.x * blockDim.x + threadIdx.x;  // [0, 2*2*128*4)
    if (idx >= 2 * 2 * EDIM * NHEAD) return;
    int h  = idx % NHEAD;
    int k  = (idx / NHEAD) % EDIM;
    int sd = (idx / (NHEAD * EDIM)) % 2;
    int l  = idx / (NHEAD * EDIM * 2);
    const float* w = l ? w1 : w0;
    const float* a = l ? (sd ? ad1 : as1) : (sd ? ad0 : as0);
    float s = 0.f;
#pragma unroll
    for (int d = 0; d < DHEAD; ++d)
        s += w[k * EDIM + h * DHEAD + d] * a[h * DHEAD + d];
    g_wa[l][sd][k][h] = s;
}

__global__ __launch_bounds__(128) void gnn_kernel(
    const float* __restrict__ obs,
    const float* __restrict__ Wv, const float* __restrict__ bv,
    const float* __restrict__ Wp, const float* __restrict__ bp,
    const float* __restrict__ w0, const float* __restrict__ w1,
    float* __restrict__ out)
{
    const int b    = blockIdx.x;
    const int t    = threadIdx.x;   // embedding column this thread owns
    const int lane = t & 31;
    const int warp = t >> 5;        // == head for the attention phase

    __shared__ float s_obs[OBSD];
    __shared__ float s_x[NTOK][XPAD];
    __shared__ float s_h[NTOK][XPAD];
    __shared__ float s_as[NTOK][NHEAD];
    __shared__ float s_ad[NTOK][NHEAD];
    __shared__ float s_alive[NTOK];
    __shared__ float s_inv;

    // ---- load observation row into SMEM (vectorized) ----
    {
        const float4* src = (const float4*)(obs + (size_t)b * OBSD);
        float4* dst = (float4*)s_obs;
#pragma unroll
        for (int i = t; i < OBSD / 4; i += 128) dst[i] = src[i];
    }
    __syncthreads();

    // ---- alive mask + count (warp 0) ----
    if (warp == 0) {
        float raw = s_obs[N_VEH * DVEH + N_PED * DPED + lane];
        int a = (raw >= 0.5f) ? 1 : 0;
        unsigned m = __ballot_sync(0xffffffffu, a);
        int cnt = __popc(m);
        if (cnt == 0) { a = 1; cnt = NTOK; }   // all-dead fallback -> all alive
        s_alive[lane] = (float)a;
        if (lane == 0) s_inv = 1.0f / (float)cnt;
    }

    // ---- token embeddings: x[n][t] ----
    {
        float acc[16];
        float bvt = bv[t];
#pragma unroll
        for (int n = 0; n < 16; ++n) acc[n] = bvt;
        for (int d = 0; d < DVEH; ++d) {
            float w = Wv[d * EDIM + t];
#pragma unroll
            for (int n = 0; n < 16; ++n) acc[n] = fmaf(s_obs[n * DVEH + d], w, acc[n]);
        }
#pragma unroll
        for (int n = 0; n < 16; ++n) s_x[n][t] = acc[n];

        float bpt = bp[t];
#pragma unroll
        for (int n = 0; n < 16; ++n) acc[n] = bpt;
        for (int d = 0; d < DPED; ++d) {
            float w = Wp[d * EDIM + t];
#pragma unroll
            for (int n = 0; n < 16; ++n)
                acc[n] = fmaf(s_obs[N_VEH * DVEH + n * DPED + d], w, acc[n]);
        }
#pragma unroll
        for (int n = 0; n < 16; ++n) s_x[16 + n][t] = acc[n];
    }
    __syncthreads();

    // ---- two GAT layers ----
    for (int l = 0; l < 2; ++l) {
        const float* __restrict__ w = l ? w1 : w0;

        // h = x @ w   (thread owns column t, 32 row accumulators)
        {
            float acc[NTOK];
#pragma unroll
            for (int n = 0; n < NTOK; ++n) acc[n] = 0.f;
            for (int k = 0; k < EDIM; k += 4) {
                float wv0 = w[(k + 0) * EDIM + t];
                float wv1 = w[(k + 1) * EDIM + t];
                float wv2 = w[(k + 2) * EDIM + t];
                float wv3 = w[(k + 3) * EDIM + t];
#pragma unroll
                for (int n = 0; n < NTOK; ++n) {
                    float4 xv = *(const float4*)&s_x[n][k];
                    acc[n] = fmaf(xv.x, wv0,
                             fmaf(xv.y, wv1,
                             fmaf(xv.z, wv2,
                             fmaf(xv.w, wv3, acc[n]))));
                }
            }
#pragma unroll
            for (int n = 0; n < NTOK; ++n) s_h[n][t] = acc[n];
        }

        // alpha_src / alpha_dst via folded weights: thread -> (n = t>>2, h = t&3)
        {
            int n  = t >> 2;
            int hh = t & 3;
            float as = 0.f, ad = 0.f;
            for (int k = 0; k < EDIM; ++k) {
                float xv = s_x[n][k];           // broadcast within 4-thread groups
                as = fmaf(xv, g_wa[l][0][k][hh], as);
                ad = fmaf(xv, g_wa[l][1][k][hh], ad);
            }
            s_as[n][hh] = as;
            s_ad[n][hh] = ad;
        }
        __syncthreads();

        // attention + aggregation + ELU. warp = head, lane = source token j.
        {
            float ad_l    = s_ad[lane][warp];
            float alive_l = s_alive[lane];
            bool  is_alive = alive_l > 0.5f;

            for (int i = 0; i < NTOK; ++i) {
                float as_i = s_as[i][warp];
                float e = as_i + ad_l;
                e = (e > 0.f) ? e : 0.2f * e;                 // leaky relu
                float eM = is_alive ? e : -1e30f;
                float m = eM;
#pragma unroll
                for (int o = 16; o > 0; o >>= 1)
                    m = fmaxf(m, __shfl_xor_sync(0xffffffffu, m, o));
                float p = is_alive ? __expf(e - m) : 0.f;
                float ps = p;
#pragma unroll
                for (int o = 16; o > 0; o >>= 1)
                    ps += __shfl_xor_sync(0xffffffffu, ps, o);
                float inv = 1.0f / ps;

                float o_acc = 0.f;
#pragma unroll
                for (int j = 0; j < NTOK; ++j) {
                    float pj = __shfl_sync(0xffffffffu, p, j);
                    o_acc = fmaf(pj, s_h[j][t], o_acc);
                }
                o_acc *= inv;
                // ELU
                s_x[i][t] = (o_acc > 0.f) ? o_acc : (__expf(o_acc) - 1.f);
            }
        }
        __syncthreads();
    }

    // ---- masked mean pooling ----
    {
        float acc = 0.f;
#pragma unroll
        for (int i = 0; i < NTOK; ++i)
            acc = fmaf(s_alive[i], s_x[i][t], acc);
        out[(size_t)b * EDIM + t] = acc * s_inv;
    }
}

extern "C" void kernel_launch(void* const* d_in, const int* in_sizes, int n_in,
                              void* d_out, int out_size) {
    const float* obs = (const float*)d_in[0];
    const float* Wv  = (const float*)d_in[1];
    const float* bv  = (const float*)d_in[2];
    const float* Wp  = (const float*)d_in[3];
    const float* bp  = (const float*)d_in[4];
    const float* w0  = (const float*)d_in[5];
    const float* as0 = (const float*)d_in[6];
    const float* ad0 = (const float*)d_in[7];
    const float* w1  = (const float*)d_in[8];
    const float* as1 = (const float*)d_in[9];
    const float* ad1 = (const float*)d_in[10];
    float* out = (float*)d_out;

    int B = in_sizes[0] / OBSD;

    fold_kernel<<<8, 256>>>(w0, as0, ad0, w1, as1, ad1);
    gnn_kernel<<<B, 128>>>(obs, Wv, bv, Wp, bp, w0, w1, out);
}

// round 2
// speedup vs baseline: 1.4207x; 1.4207x over previous
#include <cuda_runtime.h>

#define N_VEH 16
#define N_PED 16
#define NTOK  32
#define DVEH  40
#define DPED  24
#define EDIM  128
#define NHEAD 4
#define OBSD  1056   // 16*40 + 16*24 + 32
#define XPAD  132    // 128 + 4 padding (bank-conflict-free rows, float4 aligned)
#define APAD  36     // attn row stride (mult of 4, 4-way-max conflicts on STS)

// Folded attention weights: wa2[layer][k][head] = (src_fold, dst_fold)
__device__ float2 g_wa2[2][EDIM][NHEAD];

__global__ void fold_kernel(const float* __restrict__ w0,
                            const float* __restrict__ as0, const float* __restrict__ ad0,
                            const float* __restrict__ w1,
                            const float* __restrict__ as1, const float* __restrict__ ad1) {
    int idx = blockIdx.x * blockDim.x + threadIdx.x;  // [0, 2*128*4)
    if (idx >= 2 * EDIM * NHEAD) return;
    int h = idx & 3;
    int k = (idx >> 2) & 127;
    int l = idx >> 9;
    const float* w  = l ? w1  : w0;
    const float* as = l ? as1 : as0;
    const float* ad = l ? ad1 : ad0;
    float ss = 0.f, sd = 0.f;
#pragma unroll
    for (int d = 0; d < 32; ++d) {
        float wv = w[k * EDIM + h * 32 + d];
        ss = fmaf(wv, as[h * 32 + d], ss);
        sd = fmaf(wv, ad[h * 32 + d], sd);
    }
    g_wa2[l][k][h] = make_float2(ss, sd);
}

__global__ __launch_bounds__(128) void gnn_kernel(
    const float* __restrict__ obs,
    const float* __restrict__ Wv, const float* __restrict__ bv,
    const float* __restrict__ Wp, const float* __restrict__ bp,
    const float* __restrict__ w0, const float* __restrict__ w1,
    float* __restrict__ out)
{
    const int b    = blockIdx.x;
    const int t    = threadIdx.x;
    const int lane = t & 31;
    const int warp = t >> 5;

    // dynamic smem: s_x[32][132] | s_h[32][132] | s_attn[4][32][36] (aliases s_obs)
    extern __shared__ float smem[];
    float (*s_x)[XPAD] = (float (*)[XPAD])smem;                       // 4224 floats
    float (*s_h)[XPAD] = (float (*)[XPAD])(smem + NTOK * XPAD);      // 4224 floats
    float (*s_attn)[NTOK][APAD] =
        (float (*)[NTOK][APAD])(smem + 2 * NTOK * XPAD);             // 4608 floats
    float* s_obs = (float*)s_attn;                                    // alias (1056 <= 4608)

    __shared__ float s_as[NTOK][NHEAD];
    __shared__ float s_adt[NHEAD][NTOK];   // transposed for float4 loads
    __shared__ float s_bias[NTOK];         // 0 if alive else -1e30
    __shared__ float s_alive[NTOK];
    __shared__ float s_inv;

    // ---- load observation row (vectorized) ----
    {
        const float4* src = (const float4*)(obs + (size_t)b * OBSD);
        float4* dst = (float4*)s_obs;
        for (int i = t; i < OBSD / 4; i += 128) dst[i] = src[i];
    }
    __syncthreads();

    // ---- alive mask (warp 0) ----
    if (warp == 0) {
        float raw = s_obs[N_VEH * DVEH + N_PED * DPED + lane];
        int a = (raw >= 0.5f) ? 1 : 0;
        unsigned m = __ballot_sync(0xffffffffu, a);
        int cnt = __popc(m);
        if (cnt == 0) { a = 1; cnt = NTOK; }
        s_alive[lane] = (float)a;
        s_bias[lane]  = a ? 0.f : -1e30f;
        if (lane == 0) s_inv = 1.0f / (float)cnt;
    }

    // ---- token embeddings: x[n][t] (d vectorized by 4) ----
    {
        float acc[16];
        float bvt = bv[t];
#pragma unroll
        for (int n = 0; n < 16; ++n) acc[n] = bvt;
        for (int d = 0; d < DVEH; d += 4) {
            float wq0 = Wv[(d + 0) * EDIM + t];
            float wq1 = Wv[(d + 1) * EDIM + t];
            float wq2 = Wv[(d + 2) * EDIM + t];
            float wq3 = Wv[(d + 3) * EDIM + t];
#pragma unroll
            for (int n = 0; n < 16; ++n) {
                float4 ov = *(const float4*)&s_obs[n * DVEH + d];
                acc[n] = fmaf(ov.x, wq0, fmaf(ov.y, wq1,
                         fmaf(ov.z, wq2, fmaf(ov.w, wq3, acc[n]))));
            }
        }
#pragma unroll
        for (int n = 0; n < 16; ++n) s_x[n][t] = acc[n];

        float bpt = bp[t];
#pragma unroll
        for (int n = 0; n < 16; ++n) acc[n] = bpt;
        for (int d = 0; d < DPED; d += 4) {
            float wq0 = Wp[(d + 0) * EDIM + t];
            float wq1 = Wp[(d + 1) * EDIM + t];
            float wq2 = Wp[(d + 2) * EDIM + t];
            float wq3 = Wp[(d + 3) * EDIM + t];
#pragma unroll
            for (int n = 0; n < 16; ++n) {
                float4 ov = *(const float4*)&s_obs[N_VEH * DVEH + n * DPED + d];
                acc[n] = fmaf(ov.x, wq0, fmaf(ov.y, wq1,
                         fmaf(ov.z, wq2, fmaf(ov.w, wq3, acc[n]))));
            }
        }
#pragma unroll
        for (int n = 0; n < 16; ++n) s_x[16 + n][t] = acc[n];
    }
    __syncthreads();

    // ---- two GAT layers ----
    for (int l = 0; l < 2; ++l) {
        const float* __restrict__ w = l ? w1 : w0;

        // Phase A1: h = x @ w. Thread owns cols {lane, lane+32, lane+64, lane+96},
        // tokens {warp*8 .. warp*8+7}. 16 FMA per x-float4.
        {
            float acc[4][8];
#pragma unroll
            for (int g = 0; g < 4; ++g)
#pragma unroll
                for (int nn = 0; nn < 8; ++nn) acc[g][nn] = 0.f;

            const int n0 = warp * 8;
            for (int k = 0; k < EDIM; k += 4) {
                float4 xv[8];
#pragma unroll
                for (int nn = 0; nn < 8; ++nn)
                    xv[nn] = *(const float4*)&s_x[n0 + nn][k];
#pragma unroll
                for (int kk = 0; kk < 4; ++kk) {
                    const float* wr = w + (k + kk) * EDIM;
                    float wv0 = wr[lane];
                    float wv1 = wr[lane + 32];
                    float wv2 = wr[lane + 64];
                    float wv3 = wr[lane + 96];
#pragma unroll
                    for (int nn = 0; nn < 8; ++nn) {
                        float xk = ((const float*)&xv[nn])[kk];
                        acc[0][nn] = fmaf(xk, wv0, acc[0][nn]);
                        acc[1][nn] = fmaf(xk, wv1, acc[1][nn]);
                        acc[2][nn] = fmaf(xk, wv2, acc[2][nn]);
                        acc[3][nn] = fmaf(xk, wv3, acc[3][nn]);
                    }
                }
            }
#pragma unroll
            for (int g = 0; g < 4; ++g)
#pragma unroll
                for (int nn = 0; nn < 8; ++nn)
                    s_h[n0 + nn][lane + 32 * g] = acc[g][nn];
        }

        // Phase A2: folded alpha_src/alpha_dst. Thread -> (n = t>>2, h = t&3).
        {
            int an = t >> 2;
            int ah = t & 3;
            float as = 0.f, ad = 0.f;
            for (int k = 0; k < EDIM; k += 4) {
                float4 xv = *(const float4*)&s_x[an][k];
#pragma unroll
                for (int kk = 0; kk < 4; ++kk) {
                    float2 wv = g_wa2[l][k + kk][ah];
                    float xk = ((const float*)&xv)[kk];
                    as = fmaf(xk, wv.x, as);
                    ad = fmaf(xk, wv.y, ad);
                }
            }
            s_as[an][ah]  = as;
            s_adt[ah][an] = ad;
        }
        __syncthreads();

        // Phase B: shuffle-free softmax. warp = head, lane = dst row i.
        // Full row kept in registers; alive mask folded as additive -1e30 bias.
        {
            float as_i = s_as[lane][warp];
            float e[32];
#pragma unroll
            for (int jj = 0; jj < 8; ++jj) {
                float4 ad4 = *(const float4*)&s_adt[warp][4 * jj];
                float4 b4  = *(const float4*)&s_bias[4 * jj];
                float v;
                v = as_i + ad4.x; e[4 * jj + 0] = ((v > 0.f) ? v : 0.2f * v) + b4.x;
                v = as_i + ad4.y; e[4 * jj + 1] = ((v > 0.f) ? v : 0.2f * v) + b4.y;
                v = as_i + ad4.z; e[4 * jj + 2] = ((v > 0.f) ? v : 0.2f * v) + b4.z;
                v = as_i + ad4.w; e[4 * jj + 3] = ((v > 0.f) ? v : 0.2f * v) + b4.w;
            }
            // max via 4 parallel chains
            float m0 = e[0], m1 = e[1], m2 = e[2], m3 = e[3];
#pragma unroll
            for (int j = 4; j < 32; j += 4) {
                m0 = fmaxf(m0, e[j]); m1 = fmaxf(m1, e[j + 1]);
                m2 = fmaxf(m2, e[j + 2]); m3 = fmaxf(m3, e[j + 3]);
            }
            float m = fmaxf(fmaxf(m0, m1), fmaxf(m2, m3));
            // exp + sum (4 chains); masked entries: exp(-1e30 - m) == 0
            float s0 = 0.f, s1 = 0.f, s2 = 0.f, s3 = 0.f;
#pragma unroll
            for (int j = 0; j < 32; j += 4) {
                e[j]     = __expf(e[j] - m);     s0 += e[j];
                e[j + 1] = __expf(e[j + 1] - m); s1 += e[j + 1];
                e[j + 2] = __expf(e[j + 2] - m); s2 += e[j + 2];
                e[j + 3] = __expf(e[j + 3] - m); s3 += e[j + 3];
            }
            float inv = __fdividef(1.0f, (s0 + s1) + (s2 + s3));
#pragma unroll
            for (int jj = 0; jj < 8; ++jj) {
                float4 q = make_float4(e[4 * jj] * inv, e[4 * jj + 1] * inv,
                                       e[4 * jj + 2] * inv, e[4 * jj + 3] * inv);
                *(float4*)&s_attn[warp][lane][4 * jj] = q;
            }
        }
        __syncthreads();

        // Phase C: aggregation out[i][t] = sum_j attn[i][j] * h[j][t], then ELU.
        {
            float h_reg[32];
#pragma unroll
            for (int j = 0; j < 32; ++j) h_reg[j] = s_h[j][t];

            for (int i = 0; i < NTOK; ++i) {
                float a0 = 0.f, a1 = 0.f, a2 = 0.f, a3 = 0.f;
#pragma unroll
                for (int jj = 0; jj < 8; ++jj) {
                    float4 p4 = *(const float4*)&s_attn[warp][i][4 * jj];
                    a0 = fmaf(p4.x, h_reg[4 * jj + 0], a0);
                    a1 = fmaf(p4.y, h_reg[4 * jj + 1], a1);
                    a2 = fmaf(p4.z, h_reg[4 * jj + 2], a2);
                    a3 = fmaf(p4.w, h_reg[4 * jj + 3], a3);
                }
                float o = (a0 + a1) + (a2 + a3);
                s_x[i][t] = (o > 0.f) ? o : (__expf(o) - 1.0f);   // ELU
            }
        }
        __syncthreads();
    }

    // ---- masked mean pooling ----
    {
        float acc = 0.f;
#pragma unroll
        for (int i = 0; i < NTOK; ++i)
            acc = fmaf(s_alive[i], s_x[i][t], acc);
        out[(size_t)b * EDIM + t] = acc * s_inv;
    }
}

extern "C" void kernel_launch(void* const* d_in, const int* in_sizes, int n_in,
                              void* d_out, int out_size) {
    const float* obs = (const float*)d_in[0];
    const float* Wv  = (const float*)d_in[1];
    const float* bv  = (const float*)d_in[2];
    const float* Wp  = (const float*)d_in[3];
    const float* bp  = (const float*)d_in[4];
    const float* w0  = (const float*)d_in[5];
    const float* as0 = (const float*)d_in[6];
    const float* ad0 = (const float*)d_in[7];
    const float* w1  = (const float*)d_in[8];
    const float* as1 = (const float*)d_in[9];
    const float* ad1 = (const float*)d_in[10];
    float* out = (float*)d_out;

    int B = in_sizes[0] / OBSD;

    size_t shmem = (size_t)(2 * NTOK * XPAD + NHEAD * NTOK * APAD) * sizeof(float); // 52224 B
    cudaFuncSetAttribute(gnn_kernel, cudaFuncAttributeMaxDynamicSharedMemorySize, (int)shmem);

    fold_kernel<<<4, 256>>>(w0, as0, ad0, w1, as1, ad1);
    gnn_kernel<<<B, 128, shmem>>>(obs, Wv, bv, Wp, bp, w0, w1, out);
}

// round 5
// speedup vs baseline: 1.6547x; 1.1647x over previous
#include <cuda_runtime.h>

#define N_VEH 16
#define N_PED 16
#define NTOK  32
#define DVEH  40
#define DPED  24
#define EDIM  128
#define NHEAD 4
#define OBSD  1056   // 16*40 + 16*24 + 32

// XOR-4 swizzled addressing, row stride exactly 128 floats (no padding).
#define XS(row, col) (((row) << 7) + ((((col) + ((row) << 2)) & 127)))
// Swizzled attention addressing, per-head 32x32, row stride exactly 32.
#define AS(h, i, j)  (((h) << 10) + ((i) << 5) + ((((j) + ((i) << 2)) & 31)))

// Folded attention weights: per (layer, head), k-major float2 (src,dst) pairs,
// stored as float4 covering two consecutive k.
__device__ float4 g_wa4[2][NHEAD][EDIM / 2];

__global__ void fold_kernel(const float* __restrict__ w0,
                            const float* __restrict__ as0, const float* __restrict__ ad0,
                            const float* __restrict__ w1,
                            const float* __restrict__ as1, const float* __restrict__ ad1) {
    int idx = blockIdx.x * blockDim.x + threadIdx.x;  // [0, 2*4*128)
    if (idx >= 2 * NHEAD * EDIM) return;
    int k = idx & 127;
    int h = (idx >> 7) & 3;
    int l = idx >> 9;
    const float* w  = l ? w1  : w0;
    const float* as = l ? as1 : as0;
    const float* ad = l ? ad1 : ad0;
    float ss = 0.f, sd = 0.f;
#pragma unroll
    for (int d = 0; d < 32; ++d) {
        float wv = w[k * EDIM + h * 32 + d];
        ss = fmaf(wv, as[h * 32 + d], ss);
        sd = fmaf(wv, ad[h * 32 + d], sd);
    }
    float2* dst = (float2*)&g_wa4[l][h][0];
    dst[k] = make_float2(ss, sd);
}

__global__ __launch_bounds__(128, 6) void gnn_kernel(
    const float* __restrict__ obs,
    const float* __restrict__ Wv, const float* __restrict__ bv,
    const float* __restrict__ Wp, const float* __restrict__ bp,
    const float* __restrict__ w0, const float* __restrict__ w1,
    float* __restrict__ out)
{
    const int b    = blockIdx.x;
    const int t    = threadIdx.x;
    const int lane = t & 31;
    const int warp = t >> 5;

    // Two 4096-float buffers, ping-ponged. Attn aliases the dead x buffer.
    extern __shared__ float smem[];
    float* bufP = smem;
    float* bufQ = smem + 4096;

    __shared__ float s_as[NTOK][NHEAD];
    __shared__ float s_adt[NHEAD][NTOK];
    __shared__ float s_bias[NTOK];
    __shared__ float s_alive[NTOK];
    __shared__ float s_inv;

    // ---- stage observation row into bufQ (dead until layer-0 phase A1) ----
    {
        const float4* src = (const float4*)(obs + (size_t)b * OBSD);
        float4* dst = (float4*)bufQ;
        for (int i = t; i < OBSD / 4; i += 128) dst[i] = src[i];
    }
    __syncthreads();
    const float* s_obs = bufQ;

    // ---- alive mask (warp 0) ----
    if (warp == 0) {
        float raw = s_obs[N_VEH * DVEH + N_PED * DPED + lane];
        int a = (raw >= 0.5f) ? 1 : 0;
        unsigned m = __ballot_sync(0xffffffffu, a);
        int cnt = __popc(m);
        if (cnt == 0) { a = 1; cnt = NTOK; }
        s_alive[lane] = (float)a;
        s_bias[lane]  = a ? 0.f : -1e30f;
        if (lane == 0) s_inv = 1.0f / (float)cnt;
    }

    // ---- token embeddings into bufP (swizzled) ----
    {
        float acc[16];
        float bvt = bv[t];
#pragma unroll
        for (int n = 0; n < 16; ++n) acc[n] = bvt;
        for (int d = 0; d < DVEH; d += 4) {
            float wq0 = Wv[(d + 0) * EDIM + t];
            float wq1 = Wv[(d + 1) * EDIM + t];
            float wq2 = Wv[(d + 2) * EDIM + t];
            float wq3 = Wv[(d + 3) * EDIM + t];
#pragma unroll
            for (int n = 0; n < 16; ++n) {
                float4 ov = *(const float4*)&s_obs[n * DVEH + d];
                acc[n] = fmaf(ov.x, wq0, fmaf(ov.y, wq1,
                         fmaf(ov.z, wq2, fmaf(ov.w, wq3, acc[n]))));
            }
        }
        float accp[16];
        float bpt = bp[t];
#pragma unroll
        for (int n = 0; n < 16; ++n) accp[n] = bpt;
        for (int d = 0; d < DPED; d += 4) {
            float wq0 = Wp[(d + 0) * EDIM + t];
            float wq1 = Wp[(d + 1) * EDIM + t];
            float wq2 = Wp[(d + 2) * EDIM + t];
            float wq3 = Wp[(d + 3) * EDIM + t];
#pragma unroll
            for (int n = 0; n < 16; ++n) {
                float4 ov = *(const float4*)&s_obs[N_VEH * DVEH + n * DPED + d];
                accp[n] = fmaf(ov.x, wq0, fmaf(ov.y, wq1,
                          fmaf(ov.z, wq2, fmaf(ov.w, wq3, accp[n]))));
            }
        }
        __syncthreads();   // obs (in bufQ) fully consumed before bufP/bufQ writes race
#pragma unroll
        for (int n = 0; n < 16; ++n) bufP[XS(n, t)] = acc[n];
#pragma unroll
        for (int n = 0; n < 16; ++n) bufP[XS(16 + n, t)] = accp[n];
    }
    __syncthreads();

    float* xb = bufP;   // current x
    float* hb = bufQ;   // h target / next x target

    // ---- two GAT layers ----
    for (int l = 0; l < 2; ++l) {
        const float* __restrict__ w = l ? w1 : w0;

        // Phase A1: h = x @ w. Thread owns 4 consecutive cols 4*lane..4*lane+3,
        // tokens warp*8..warp*8+7. w loads are LDG.128.
        {
            float acc[8][4];
#pragma unroll
            for (int nn = 0; nn < 8; ++nn)
#pragma unroll
                for (int g = 0; g < 4; ++g) acc[nn][g] = 0.f;

            const int n0 = warp * 8;
            const int c0 = lane * 4;
#pragma unroll 2
            for (int k = 0; k < EDIM; k += 4) {
                float4 wv0 = *(const float4*)&w[(k + 0) * EDIM + c0];
                float4 wv1 = *(const float4*)&w[(k + 1) * EDIM + c0];
                float4 wv2 = *(const float4*)&w[(k + 2) * EDIM + c0];
                float4 wv3 = *(const float4*)&w[(k + 3) * EDIM + c0];
#pragma unroll
                for (int nn = 0; nn < 8; ++nn) {
                    float4 xv = *(const float4*)&xb[XS(n0 + nn, k)];
                    acc[nn][0] = fmaf(xv.x, wv0.x, fmaf(xv.y, wv1.x,
                                 fmaf(xv.z, wv2.x, fmaf(xv.w, wv3.x, acc[nn][0]))));
                    acc[nn][1] = fmaf(xv.x, wv0.y, fmaf(xv.y, wv1.y,
                                 fmaf(xv.z, wv2.y, fmaf(xv.w, wv3.y, acc[nn][1]))));
                    acc[nn][2] = fmaf(xv.x, wv0.z, fmaf(xv.y, wv1.z,
                                 fmaf(xv.z, wv2.z, fmaf(xv.w, wv3.z, acc[nn][2]))));
                    acc[nn][3] = fmaf(xv.x, wv0.w, fmaf(xv.y, wv1.w,
                                 fmaf(xv.z, wv2.w, fmaf(xv.w, wv3.w, acc[nn][3]))));
                }
            }
#pragma unroll
            for (int nn = 0; nn < 8; ++nn)
                *(float4*)&hb[XS(n0 + nn, c0)] =
                    make_float4(acc[nn][0], acc[nn][1], acc[nn][2], acc[nn][3]);
        }

        // Phase A2: folded alphas. warp = head, lane = token.
        {
            float as = 0.f, ad = 0.f;
#pragma unroll 2
            for (int k = 0; k < EDIM; k += 4) {
                float4 xv = *(const float4*)&xb[XS(lane, k)];
                float4 q0 = g_wa4[l][warp][(k >> 1) + 0];   // (s_k,d_k,s_k1,d_k1)
                float4 q1 = g_wa4[l][warp][(k >> 1) + 1];
                as = fmaf(xv.x, q0.x, fmaf(xv.y, q0.z, as));
                ad = fmaf(xv.x, q0.y, fmaf(xv.y, q0.w, ad));
                as = fmaf(xv.z, q1.x, fmaf(xv.w, q1.z, as));
                ad = fmaf(xv.z, q1.y, fmaf(xv.w, q1.w, ad));
            }
            s_as[lane][warp]  = as;
            s_adt[warp][lane] = ad;
        }
        __syncthreads();   // x fully consumed; attn may now overwrite xb

        // Phase B: shuffle-free softmax. warp = head, lane = dst row i.
        // Writes normalized probs into xb (aliased attn, swizzled).
        {
            float as_i = s_as[lane][warp];
            float e[32];
#pragma unroll
            for (int jj = 0; jj < 8; ++jj) {
                float4 ad4 = *(const float4*)&s_adt[warp][4 * jj];
                float4 b4  = *(const float4*)&s_bias[4 * jj];
                float v;
                v = as_i + ad4.x; e[4 * jj + 0] = ((v > 0.f) ? v : 0.2f * v) + b4.x;
                v = as_i + ad4.y; e[4 * jj + 1] = ((v > 0.f) ? v : 0.2f * v) + b4.y;
                v = as_i + ad4.z; e[4 * jj + 2] = ((v > 0.f) ? v : 0.2f * v) + b4.z;
                v = as_i + ad4.w; e[4 * jj + 3] = ((v > 0.f) ? v : 0.2f * v) + b4.w;
            }
            float m0 = e[0], m1 = e[1], m2 = e[2], m3 = e[3];
#pragma unroll
            for (int j = 4; j < 32; j += 4) {
                m0 = fmaxf(m0, e[j]);     m1 = fmaxf(m1, e[j + 1]);
                m2 = fmaxf(m2, e[j + 2]); m3 = fmaxf(m3, e[j + 3]);
            }
            float m = fmaxf(fmaxf(m0, m1), fmaxf(m2, m3));
            float s0 = 0.f, s1 = 0.f, s2 = 0.f, s3 = 0.f;
#pragma unroll
            for (int j = 0; j < 32; j += 4) {
                e[j]     = __expf(e[j] - m);     s0 += e[j];
                e[j + 1] = __expf(e[j + 1] - m); s1 += e[j + 1];
                e[j + 2] = __expf(e[j + 2] - m); s2 += e[j + 2];
                e[j + 3] = __expf(e[j + 3] - m); s3 += e[j + 3];
            }
            float inv = __fdividef(1.0f, (s0 + s1) + (s2 + s3));
#pragma unroll
            for (int jj = 0; jj < 8; ++jj)
                *(float4*)&xb[AS(warp, lane, 4 * jj)] =
                    make_float4(e[4 * jj] * inv, e[4 * jj + 1] * inv,
                                e[4 * jj + 2] * inv, e[4 * jj + 3] * inv);
        }
        __syncthreads();

        // Phase C: out[i][t] = sum_j attn[i][j] * h[j][t], ELU, write into hb.
        // Each thread touches only its own column of hb -> no barrier needed.
        {
            float h_reg[32];
#pragma unroll
            for (int j = 0; j < 32; ++j) h_reg[j] = hb[XS(j, t)];

#pragma unroll 2
            for (int i = 0; i < NTOK; ++i) {
                float a0 = 0.f, a1 = 0.f, a2 = 0.f, a3 = 0.f;
#pragma unroll
                for (int jj = 0; jj < 8; ++jj) {
                    float4 p4 = *(const float4*)&xb[AS(warp, i, 4 * jj)];
                    a0 = fmaf(p4.x, h_reg[4 * jj + 0], a0);
                    a1 = fmaf(p4.y, h_reg[4 * jj + 1], a1);
                    a2 = fmaf(p4.z, h_reg[4 * jj + 2], a2);
                    a3 = fmaf(p4.w, h_reg[4 * jj + 3], a3);
                }
                float o = (a0 + a1) + (a2 + a3);
                hb[XS(i, t)] = (o > 0.f) ? o : (__expf(o) - 1.0f);   // ELU
            }
        }
        __syncthreads();

        // swap roles: new x is in hb, old attn buffer becomes next h target
        float* tmp = xb; xb = hb; hb = tmp;
    }

    // ---- masked mean pooling (final x is in xb) ----
    {
        float acc = 0.f;
#pragma unroll
        for (int i = 0; i < NTOK; ++i)
            acc = fmaf(s_alive[i], xb[XS(i, t)], acc);
        out[(size_t)b * EDIM + t] = acc * s_inv;
    }
}

extern "C" void kernel_launch(void* const* d_in, const int* in_sizes, int n_in,
                              void* d_out, int out_size) {
    const float* obs = (const float*)d_in[0];
    const float* Wv  = (const float*)d_in[1];
    const float* bv  = (const float*)d_in[2];
    const float* Wp  = (const float*)d_in[3];
    const float* bp  = (const float*)d_in[4];
    const float* w0  = (const float*)d_in[5];
    const float* as0 = (const float*)d_in[6];
    const float* ad0 = (const float*)d_in[7];
    const float* w1  = (const float*)d_in[8];
    const float* as1 = (const float*)d_in[9];
    const float* ad1 = (const float*)d_in[10];
    float* out = (float*)d_out;

    int B = in_sizes[0] / OBSD;

    size_t shmem = 8192 * sizeof(float);   // 32 KB
    cudaFuncSetAttribute(gnn_kernel, cudaFuncAttributeMaxDynamicSharedMemorySize, (int)shmem);

    fold_kernel<<<4, 256>>>(w0, as0, ad0, w1, as1, ad1);
    gnn_kernel<<<B, 128, shmem>>>(obs, Wv, bv, Wp, bp, w0, w1, out);
}

// round 6
// speedup vs baseline: 2.7581x; 1.6668x over previous
#include <cuda_runtime.h>
#include <cstdint>

#define N_VEH 16
#define N_PED 16
#define NTOK  32
#define DVEH  40
#define DPED  24
#define EDIM  128
#define NHEAD 4
#define OBSD  1056   // 16*40 + 16*24 + 32

// XOR-4 swizzled addressing, row stride exactly 128 floats (no padding).
#define XS(row, col) (((row) << 7) + ((((col) + ((row) << 2)) & 127)))
// Swizzled attention addressing, per-head 32x32, row stride exactly 32.
#define AS(h, i, j)  (((h) << 10) + ((i) << 5) + ((((j) + ((i) << 2)) & 31)))

// Folded attention weights: per (layer, head), k-major float2 (src,dst) pairs.
__device__ float4 g_wa4[2][NHEAD][EDIM / 2];
// w0/w1 pre-converted to tf32 bit patterns, [layer][k][n].
__device__ uint32_t g_wt[2][EDIM][EDIM];

__device__ __forceinline__ uint32_t f2tf32(float f) {
    uint32_t r;
    asm("cvt.rna.tf32.f32 %0, %1;" : "=r"(r) : "f"(f));
    return r;
}

__device__ __forceinline__ void mma_tf32(float* c, const uint32_t* a,
                                         uint32_t b0, uint32_t b1) {
    asm("mma.sync.aligned.m16n8k8.row.col.f32.tf32.tf32.f32 "
        "{%0,%1,%2,%3}, {%4,%5,%6,%7}, {%8,%9}, {%0,%1,%2,%3};"
        : "+f"(c[0]), "+f"(c[1]), "+f"(c[2]), "+f"(c[3])
        : "r"(a[0]), "r"(a[1]), "r"(a[2]), "r"(a[3]), "r"(b0), "r"(b1));
}

__global__ void fold_kernel(const float* __restrict__ w0,
                            const float* __restrict__ as0, const float* __restrict__ ad0,
                            const float* __restrict__ w1,
                            const float* __restrict__ as1, const float* __restrict__ ad1) {
    int idx = blockIdx.x * blockDim.x + threadIdx.x;  // [0, 2*4*128)
    if (idx >= 2 * NHEAD * EDIM) return;
    int k = idx & 127;
    int h = (idx >> 7) & 3;
    int l = idx >> 9;
    const float* w  = l ? w1  : w0;
    const float* as = l ? as1 : as0;
    const float* ad = l ? ad1 : ad0;
    float ss = 0.f, sd = 0.f;
#pragma unroll
    for (int d = 0; d < 32; ++d) {
        float wv = w[k * EDIM + h * 32 + d];
        ss = fmaf(wv, as[h * 32 + d], ss);
        sd = fmaf(wv, ad[h * 32 + d], sd);
    }
    float2* dst = (float2*)&g_wa4[l][h][0];
    dst[k] = make_float2(ss, sd);
}

__global__ void cvtw_kernel(const float* __restrict__ w0,
                            const float* __restrict__ w1) {
    int idx = blockIdx.x * blockDim.x + threadIdx.x;  // [0, 2*128*128)
    if (idx >= 2 * EDIM * EDIM) return;
    int l = idx >> 14;
    int e = idx & (EDIM * EDIM - 1);
    const float* w = l ? w1 : w0;
    ((uint32_t*)g_wt)[idx] = f2tf32(w[e]);
}

__global__ __launch_bounds__(128, 6) void gnn_kernel(
    const float* __restrict__ obs,
    const float* __restrict__ Wv, const float* __restrict__ bv,
    const float* __restrict__ Wp, const float* __restrict__ bp,
    float* __restrict__ out)
{
    const int b    = blockIdx.x;
    const int t    = threadIdx.x;
    const int lane = t & 31;
    const int warp = t >> 5;
    const int gID  = lane >> 2;   // mma group id (row group)
    const int tig  = lane & 3;    // thread-in-group (col group)

    // Two 4096-float buffers, ping-ponged. Attn aliases the dead x buffer.
    extern __shared__ float smem[];
    float* bufP = smem;
    float* bufQ = smem + 4096;

    __shared__ float s_as[NTOK][NHEAD];
    __shared__ float s_adt[NHEAD][NTOK];
    __shared__ float s_bias[NTOK];
    __shared__ float s_alive[NTOK];
    __shared__ float s_inv;

    // ---- stage observation row into bufQ ----
    {
        const float4* src = (const float4*)(obs + (size_t)b * OBSD);
        float4* dst = (float4*)bufQ;
        for (int i = t; i < OBSD / 4; i += 128) dst[i] = src[i];
    }
    __syncthreads();
    const float* s_obs = bufQ;

    // ---- alive mask (warp 0) ----
    if (warp == 0) {
        float raw = s_obs[N_VEH * DVEH + N_PED * DPED + lane];
        int a = (raw >= 0.5f) ? 1 : 0;
        unsigned m = __ballot_sync(0xffffffffu, a);
        int cnt = __popc(m);
        if (cnt == 0) { a = 1; cnt = NTOK; }
        s_alive[lane] = (float)a;
        s_bias[lane]  = a ? 0.f : -1e30f;
        if (lane == 0) s_inv = 1.0f / (float)cnt;
    }

    // ---- token embeddings into bufP (swizzled, exact fp32) ----
    {
        float acc[16];
        float bvt = bv[t];
#pragma unroll
        for (int n = 0; n < 16; ++n) acc[n] = bvt;
        for (int d = 0; d < DVEH; d += 4) {
            float wq0 = Wv[(d + 0) * EDIM + t];
            float wq1 = Wv[(d + 1) * EDIM + t];
            float wq2 = Wv[(d + 2) * EDIM + t];
            float wq3 = Wv[(d + 3) * EDIM + t];
#pragma unroll
            for (int n = 0; n < 16; ++n) {
                float4 ov = *(const float4*)&s_obs[n * DVEH + d];
                acc[n] = fmaf(ov.x, wq0, fmaf(ov.y, wq1,
                         fmaf(ov.z, wq2, fmaf(ov.w, wq3, acc[n]))));
            }
        }
        float accp[16];
        float bpt = bp[t];
#pragma unroll
        for (int n = 0; n < 16; ++n) accp[n] = bpt;
        for (int d = 0; d < DPED; d += 4) {
            float wq0 = Wp[(d + 0) * EDIM + t];
            float wq1 = Wp[(d + 1) * EDIM + t];
            float wq2 = Wp[(d + 2) * EDIM + t];
            float wq3 = Wp[(d + 3) * EDIM + t];
#pragma unroll
            for (int n = 0; n < 16; ++n) {
                float4 ov = *(const float4*)&s_obs[N_VEH * DVEH + n * DPED + d];
                accp[n] = fmaf(ov.x, wq0, fmaf(ov.y, wq1,
                          fmaf(ov.z, wq2, fmaf(ov.w, wq3, accp[n]))));
            }
        }
        __syncthreads();   // obs fully consumed before overwriting buffers
#pragma unroll
        for (int n = 0; n < 16; ++n) bufP[XS(n, t)] = acc[n];
#pragma unroll
        for (int n = 0; n < 16; ++n) bufP[XS(16 + n, t)] = accp[n];
    }
    __syncthreads();

    float* xb = bufP;   // current x
    float* hb = bufQ;   // h target / next x target

    // ---- two GAT layers ----
    for (int l = 0; l < 2; ++l) {
        // Phase A1: h = x @ w via tf32 MMA. Warp owns output cols 32*warp..+31.
        {
            const int n0w = warp * 32;
            float acc[2][4][4];
#pragma unroll
            for (int mt = 0; mt < 2; ++mt)
#pragma unroll
                for (int nt = 0; nt < 4; ++nt)
#pragma unroll
                    for (int r = 0; r < 4; ++r) acc[mt][nt][r] = 0.f;

#pragma unroll 4
            for (int kt = 0; kt < 16; ++kt) {
                const int k0 = kt * 8;
                uint32_t a[2][4];
#pragma unroll
                for (int mt = 0; mt < 2; ++mt) {
                    const int r0 = mt * 16 + gID;
                    a[mt][0] = f2tf32(xb[XS(r0,     k0 + tig)]);
                    a[mt][1] = f2tf32(xb[XS(r0 + 8, k0 + tig)]);
                    a[mt][2] = f2tf32(xb[XS(r0,     k0 + tig + 4)]);
                    a[mt][3] = f2tf32(xb[XS(r0 + 8, k0 + tig + 4)]);
                }
#pragma unroll
                for (int nt = 0; nt < 4; ++nt) {
                    const int n = n0w + nt * 8 + gID;
                    uint32_t b0 = g_wt[l][k0 + tig][n];
                    uint32_t b1 = g_wt[l][k0 + tig + 4][n];
                    mma_tf32(acc[0][nt], a[0], b0, b1);
                    mma_tf32(acc[1][nt], a[1], b0, b1);
                }
            }
#pragma unroll
            for (int mt = 0; mt < 2; ++mt)
#pragma unroll
                for (int nt = 0; nt < 4; ++nt) {
                    const int r = mt * 16 + gID;
                    const int c = n0w + nt * 8 + 2 * tig;
                    *(float2*)&hb[XS(r, c)] =
                        make_float2(acc[mt][nt][0], acc[mt][nt][1]);
                    *(float2*)&hb[XS(r + 8, c)] =
                        make_float2(acc[mt][nt][2], acc[mt][nt][3]);
                }
        }

        // Phase A2: folded alphas (exact fp32). warp = head, lane = token.
        {
            float as = 0.f, ad = 0.f;
#pragma unroll 2
            for (int k = 0; k < EDIM; k += 4) {
                float4 xv = *(const float4*)&xb[XS(lane, k)];
                float4 q0 = g_wa4[l][warp][(k >> 1) + 0];
                float4 q1 = g_wa4[l][warp][(k >> 1) + 1];
                as = fmaf(xv.x, q0.x, fmaf(xv.y, q0.z, as));
                ad = fmaf(xv.x, q0.y, fmaf(xv.y, q0.w, ad));
                as = fmaf(xv.z, q1.x, fmaf(xv.w, q1.z, as));
                ad = fmaf(xv.z, q1.y, fmaf(xv.w, q1.w, ad));
            }
            s_as[lane][warp]  = as;
            s_adt[warp][lane] = ad;
        }
        __syncthreads();   // x fully consumed; attn may now overwrite xb

        // Phase B: shuffle-free softmax. warp = head, lane = dst row i.
        {
            float as_i = s_as[lane][warp];
            float e[32];
#pragma unroll
            for (int jj = 0; jj < 8; ++jj) {
                float4 ad4 = *(const float4*)&s_adt[warp][4 * jj];
                float4 b4  = *(const float4*)&s_bias[4 * jj];
                float v;
                v = as_i + ad4.x; e[4 * jj + 0] = ((v > 0.f) ? v : 0.2f * v) + b4.x;
                v = as_i + ad4.y; e[4 * jj + 1] = ((v > 0.f) ? v : 0.2f * v) + b4.y;
                v = as_i + ad4.z; e[4 * jj + 2] = ((v > 0.f) ? v : 0.2f * v) + b4.z;
                v = as_i + ad4.w; e[4 * jj + 3] = ((v > 0.f) ? v : 0.2f * v) + b4.w;
            }
            float m0 = e[0], m1 = e[1], m2 = e[2], m3 = e[3];
#pragma unroll
            for (int j = 4; j < 32; j += 4) {
                m0 = fmaxf(m0, e[j]);     m1 = fmaxf(m1, e[j + 1]);
                m2 = fmaxf(m2, e[j + 2]); m3 = fmaxf(m3, e[j + 3]);
            }
            float m = fmaxf(fmaxf(m0, m1), fmaxf(m2, m3));
            float s0 = 0.f, s1 = 0.f, s2 = 0.f, s3 = 0.f;
#pragma unroll
            for (int j = 0; j < 32; j += 4) {
                e[j]     = __expf(e[j] - m);     s0 += e[j];
                e[j + 1] = __expf(e[j + 1] - m); s1 += e[j + 1];
                e[j + 2] = __expf(e[j + 2] - m); s2 += e[j + 2];
                e[j + 3] = __expf(e[j + 3] - m); s3 += e[j + 3];
            }
            float inv = __fdividef(1.0f, (s0 + s1) + (s2 + s3));
#pragma unroll
            for (int jj = 0; jj < 8; ++jj)
                *(float4*)&xb[AS(warp, lane, 4 * jj)] =
                    make_float4(e[4 * jj] * inv, e[4 * jj + 1] * inv,
                                e[4 * jj + 2] * inv, e[4 * jj + 3] * inv);
        }
        __syncthreads();

        // Phase C: out = attn_h @ h_h via tf32 MMA (per-head 32x32x32),
        // ELU epilogue, write x' into hb (head-sliced cols -> no cross-warp race;
        // in-warp read->write ordered by final mma.sync convergence + syncwarp).
        {
            const int n0 = warp * 32;
            float acc[2][4][4];
#pragma unroll
            for (int mt = 0; mt < 2; ++mt)
#pragma unroll
                for (int nt = 0; nt < 4; ++nt)
#pragma unroll
                    for (int r = 0; r < 4; ++r) acc[mt][nt][r] = 0.f;

#pragma unroll
            for (int kt = 0; kt < 4; ++kt) {
                const int k0 = kt * 8;
                uint32_t a[2][4];
#pragma unroll
                for (int mt = 0; mt < 2; ++mt) {
                    const int r0 = mt * 16 + gID;
                    a[mt][0] = f2tf32(xb[AS(warp, r0,     k0 + tig)]);
                    a[mt][1] = f2tf32(xb[AS(warp, r0 + 8, k0 + tig)]);
                    a[mt][2] = f2tf32(xb[AS(warp, r0,     k0 + tig + 4)]);
                    a[mt][3] = f2tf32(xb[AS(warp, r0 + 8, k0 + tig + 4)]);
                }
#pragma unroll
                for (int nt = 0; nt < 4; ++nt) {
                    const int n = n0 + nt * 8 + gID;
                    uint32_t b0 = f2tf32(hb[XS(k0 + tig,     n)]);
                    uint32_t b1 = f2tf32(hb[XS(k0 + tig + 4, n)]);
                    mma_tf32(acc[0][nt], a[0], b0, b1);
                    mma_tf32(acc[1][nt], a[1], b0, b1);
                }
            }
            __syncwarp();
#pragma unroll
            for (int mt = 0; mt < 2; ++mt)
#pragma unroll
                for (int nt = 0; nt < 4; ++nt) {
                    const int r = mt * 16 + gID;
                    const int c = n0 + nt * 8 + 2 * tig;
                    float o0 = acc[mt][nt][0], o1 = acc[mt][nt][1];
                    float o2 = acc[mt][nt][2], o3 = acc[mt][nt][3];
                    o0 = (o0 > 0.f) ? o0 : (__expf(o0) - 1.0f);
                    o1 = (o1 > 0.f) ? o1 : (__expf(o1) - 1.0f);
                    o2 = (o2 > 0.f) ? o2 : (__expf(o2) - 1.0f);
                    o3 = (o3 > 0.f) ? o3 : (__expf(o3) - 1.0f);
                    *(float2*)&hb[XS(r, c)]     = make_float2(o0, o1);
                    *(float2*)&hb[XS(r + 8, c)] = make_float2(o2, o3);
                }
        }
        __syncthreads();

        // swap roles: new x is in hb
        float* tmp = xb; xb = hb; hb = tmp;
    }

    // ---- masked mean pooling (final x is in xb) ----
    {
        float acc = 0.f;
#pragma unroll
        for (int i = 0; i < NTOK; ++i)
            acc = fmaf(s_alive[i], xb[XS(i, t)], acc);
        out[(size_t)b * EDIM + t] = acc * s_inv;
    }
}

extern "C" void kernel_launch(void* const* d_in, const int* in_sizes, int n_in,
                              void* d_out, int out_size) {
    const float* obs = (const float*)d_in[0];
    const float* Wv  = (const float*)d_in[1];
    const float* bv  = (const float*)d_in[2];
    const float* Wp  = (const float*)d_in[3];
    const float* bp  = (const float*)d_in[4];
    const float* w0  = (const float*)d_in[5];
    const float* as0 = (const float*)d_in[6];
    const float* ad0 = (const float*)d_in[7];
    const float* w1  = (const float*)d_in[8];
    const float* as1 = (const float*)d_in[9];
    const float* ad1 = (const float*)d_in[10];
    float* out = (float*)d_out;

    int B = in_sizes[0] / OBSD;

    size_t shmem = 8192 * sizeof(float);   // 32 KB
    cudaFuncSetAttribute(gnn_kernel, cudaFuncAttributeMaxDynamicSharedMemorySize, (int)shmem);

    fold_kernel<<<4, 256>>>(w0, as0, ad0, w1, as1, ad1);
    cvtw_kernel<<<128, 256>>>(w0, w1);
    gnn_kernel<<<B, 128, shmem>>>(obs, Wv, bv, Wp, bp, out);
}

// round 8
// speedup vs baseline: 3.4134x; 1.2376x over previous
#include <cuda_runtime.h>
#include <cstdint>

#define N_VEH 16
#define N_PED 16
#define NTOK  32
#define DVEH  40
#define DPED  24
#define EDIM  128
#define NHEAD 4
#define OBSD  1056   // 16*40 + 16*24 + 32

// XOR-4 swizzled addressing, row stride exactly 128 floats (no padding).
#define XS(row, col) (((row) << 7) + ((((col) + ((row) << 2)) & 127)))
// Swizzled attention addressing, per-head 32x32, row stride exactly 32.
#define AS(h, i, j)  (((h) << 10) + ((i) << 5) + ((((j) + ((i) << 2)) & 31)))

// w0/w1 pre-converted to tf32 bit patterns, [layer][k][n].
__device__ uint32_t g_wt[2][EDIM][EDIM];
// Folded alpha weights as tf32, [layer][k][8]: cols 0-3 = src head, 4-7 = dst head.
__device__ uint32_t g_wtA[2][EDIM][8];

__device__ __forceinline__ uint32_t f2tf32(float f) {
    uint32_t r;
    asm("cvt.rna.tf32.f32 %0, %1;" : "=r"(r) : "f"(f));
    return r;
}
__device__ __forceinline__ float tf32r(float f) {   // tf32-rounded fp32 value
    return __uint_as_float(f2tf32(f));
}

__device__ __forceinline__ void mma_tf32(float* c, const uint32_t* a,
                                         uint32_t b0, uint32_t b1) {
    asm("mma.sync.aligned.m16n8k8.row.col.f32.tf32.tf32.f32 "
        "{%0,%1,%2,%3}, {%4,%5,%6,%7}, {%8,%9}, {%0,%1,%2,%3};"
        : "+f"(c[0]), "+f"(c[1]), "+f"(c[2]), "+f"(c[3])
        : "r"(a[0]), "r"(a[1]), "r"(a[2]), "r"(a[3]), "r"(b0), "r"(b1));
}

// Single fused prep: convert w to tf32 AND build folded alpha columns.
__global__ void prep_kernel(const float* __restrict__ w0,
                            const float* __restrict__ as0, const float* __restrict__ ad0,
                            const float* __restrict__ w1,
                            const float* __restrict__ as1, const float* __restrict__ ad1) {
    int idx = blockIdx.x * blockDim.x + threadIdx.x;   // [0, 2*128*136)
    if (idx >= 2 * EDIM * 136) return;
    int l = idx / (EDIM * 136);
    int rem = idx - l * EDIM * 136;
    int k = rem / 136;
    int c = rem - k * 136;
    const float* w = l ? w1 : w0;
    if (c < EDIM) {
        g_wt[l][k][c] = f2tf32(w[k * EDIM + c]);
    } else {
        int j = c - EDIM;          // 0..7
        int h = j & 3;
        const float* a = (j < 4) ? (l ? as1 : as0) : (l ? ad1 : ad0);
        float s = 0.f;
#pragma unroll
        for (int d = 0; d < 32; ++d)
            s = fmaf(w[k * EDIM + h * 32 + d], a[h * 32 + d], s);
        g_wtA[l][k][j] = f2tf32(s);
    }
}

__global__ __launch_bounds__(128, 6) void gnn_kernel(
    const float* __restrict__ obs,
    const float* __restrict__ Wv, const float* __restrict__ bv,
    const float* __restrict__ Wp, const float* __restrict__ bp,
    float* __restrict__ out)
{
    const int b    = blockIdx.x;
    const int t    = threadIdx.x;
    const int lane = t & 31;
    const int warp = t >> 5;
    const int gID  = lane >> 2;   // mma group id (row group)
    const int tig  = lane & 3;    // thread-in-group (col group)

    extern __shared__ float smem[];
    float* bufP = smem;
    float* bufQ = smem + 4096;

    __shared__ float s_as[NTOK][NHEAD];
    __shared__ float s_adt[NHEAD][NTOK];
    __shared__ float s_bias[NTOK];
    __shared__ float s_alive[NTOK];
    __shared__ float s_inv;

    // ---- stage observation row into bufQ ----
    {
        const float4* src = (const float4*)(obs + (size_t)b * OBSD);
        float4* dst = (float4*)bufQ;
        for (int i = t; i < OBSD / 4; i += 128) dst[i] = src[i];
    }
    __syncthreads();
    const float* s_obs = bufQ;

    // ---- alive mask (warp 0) ----
    if (warp == 0) {
        float raw = s_obs[N_VEH * DVEH + N_PED * DPED + lane];
        int a = (raw >= 0.5f) ? 1 : 0;
        unsigned m = __ballot_sync(0xffffffffu, a);
        int cnt = __popc(m);
        if (cnt == 0) { a = 1; cnt = NTOK; }
        s_alive[lane] = (float)a;
        s_bias[lane]  = a ? 0.f : -1e30f;
        if (lane == 0) s_inv = 1.0f / (float)cnt;
    }

    // ---- token embeddings into bufP (fp32 math, stored tf32-rounded) ----
    {
        float acc[16];
        float bvt = bv[t];
#pragma unroll
        for (int n = 0; n < 16; ++n) acc[n] = bvt;
        for (int d = 0; d < DVEH; d += 4) {
            float wq0 = Wv[(d + 0) * EDIM + t];
            float wq1 = Wv[(d + 1) * EDIM + t];
            float wq2 = Wv[(d + 2) * EDIM + t];
            float wq3 = Wv[(d + 3) * EDIM + t];
#pragma unroll
            for (int n = 0; n < 16; ++n) {
                float4 ov = *(const float4*)&s_obs[n * DVEH + d];
                acc[n] = fmaf(ov.x, wq0, fmaf(ov.y, wq1,
                         fmaf(ov.z, wq2, fmaf(ov.w, wq3, acc[n]))));
            }
        }
        float accp[16];
        float bpt = bp[t];
#pragma unroll
        for (int n = 0; n < 16; ++n) accp[n] = bpt;
        for (int d = 0; d < DPED; d += 4) {
            float wq0 = Wp[(d + 0) * EDIM + t];
            float wq1 = Wp[(d + 1) * EDIM + t];
            float wq2 = Wp[(d + 2) * EDIM + t];
            float wq3 = Wp[(d + 3) * EDIM + t];
#pragma unroll
            for (int n = 0; n < 16; ++n) {
                float4 ov = *(const float4*)&s_obs[N_VEH * DVEH + n * DPED + d];
                accp[n] = fmaf(ov.x, wq0, fmaf(ov.y, wq1,
                          fmaf(ov.z, wq2, fmaf(ov.w, wq3, accp[n]))));
            }
        }
        __syncthreads();   // obs fully consumed before overwriting buffers
#pragma unroll
        for (int n = 0; n < 16; ++n) bufP[XS(n, t)] = tf32r(acc[n]);
#pragma unroll
        for (int n = 0; n < 16; ++n) bufP[XS(16 + n, t)] = tf32r(accp[n]);
    }
    __syncthreads();

    float* xb = bufP;   // current x (tf32-rounded values)
    float* hb = bufQ;   // h target / next x target

    // ---- two GAT layers ----
#pragma unroll
    for (int l = 0; l < 2; ++l) {
        // Phase A1: h = x @ w via tf32 MMA; warp 0 additionally computes the
        // alpha tile x @ WA (128x8) and scatters it to s_as/s_adt.
        {
            const int n0w = warp * 32;
            float acc[2][4][4];
            float accA[2][4];
#pragma unroll
            for (int mt = 0; mt < 2; ++mt) {
#pragma unroll
                for (int nt = 0; nt < 4; ++nt)
#pragma unroll
                    for (int r = 0; r < 4; ++r) acc[mt][nt][r] = 0.f;
#pragma unroll
                for (int r = 0; r < 4; ++r) accA[mt][r] = 0.f;
            }

#pragma unroll 4
            for (int kt = 0; kt < 16; ++kt) {
                const int k0 = kt * 8;
                uint32_t a[2][4];
#pragma unroll
                for (int mt = 0; mt < 2; ++mt) {
                    const int r0 = mt * 16 + gID;
                    a[mt][0] = __float_as_uint(xb[XS(r0,     k0 + tig)]);
                    a[mt][1] = __float_as_uint(xb[XS(r0 + 8, k0 + tig)]);
                    a[mt][2] = __float_as_uint(xb[XS(r0,     k0 + tig + 4)]);
                    a[mt][3] = __float_as_uint(xb[XS(r0 + 8, k0 + tig + 4)]);
                }
#pragma unroll
                for (int nt = 0; nt < 4; ++nt) {
                    const int n = n0w + nt * 8 + gID;
                    uint32_t b0 = g_wt[l][k0 + tig][n];
                    uint32_t b1 = g_wt[l][k0 + tig + 4][n];
                    mma_tf32(acc[0][nt], a[0], b0, b1);
                    mma_tf32(acc[1][nt], a[1], b0, b1);
                }
                if (warp == 0) {
                    uint32_t b0 = g_wtA[l][k0 + tig][gID];
                    uint32_t b1 = g_wtA[l][k0 + tig + 4][gID];
                    mma_tf32(accA[0], a[0], b0, b1);
                    mma_tf32(accA[1], a[1], b0, b1);
                }
            }
#pragma unroll
            for (int mt = 0; mt < 2; ++mt)
#pragma unroll
                for (int nt = 0; nt < 4; ++nt) {
                    const int r = mt * 16 + gID;
                    const int c = n0w + nt * 8 + 2 * tig;
                    *(float2*)&hb[XS(r, c)] =
                        make_float2(tf32r(acc[mt][nt][0]), tf32r(acc[mt][nt][1]));
                    *(float2*)&hb[XS(r + 8, c)] =
                        make_float2(tf32r(acc[mt][nt][2]), tf32r(acc[mt][nt][3]));
                }
            if (warp == 0) {
#pragma unroll
                for (int mt = 0; mt < 2; ++mt) {
                    const int r = mt * 16 + gID;
#pragma unroll
                    for (int q = 0; q < 4; ++q) {
                        int row = (q < 2) ? r : (r + 8);
                        int col = 2 * tig + (q & 1);
                        float v = accA[mt][q];
                        if (col < 4) s_as[row][col] = v;
                        else         s_adt[col - 4][row] = v;
                    }
                }
            }
        }
        __syncthreads();   // x fully consumed; attn may now overwrite xb

        // Phase B: shuffle-free softmax. warp = head, lane = dst row i.
        {
            float as_i = s_as[lane][warp];
            float e[32];
#pragma unroll
            for (int jj = 0; jj < 8; ++jj) {
                float4 ad4 = *(const float4*)&s_adt[warp][4 * jj];
                float4 b4  = *(const float4*)&s_bias[4 * jj];
                float v;
                v = as_i + ad4.x; e[4 * jj + 0] = ((v > 0.f) ? v : 0.2f * v) + b4.x;
                v = as_i + ad4.y; e[4 * jj + 1] = ((v > 0.f) ? v : 0.2f * v) + b4.y;
                v = as_i + ad4.z; e[4 * jj + 2] = ((v > 0.f) ? v : 0.2f * v) + b4.z;
                v = as_i + ad4.w; e[4 * jj + 3] = ((v > 0.f) ? v : 0.2f * v) + b4.w;
            }
            float m0 = e[0], m1 = e[1], m2 = e[2], m3 = e[3];
#pragma unroll
            for (int j = 4; j < 32; j += 4) {
                m0 = fmaxf(m0, e[j]);     m1 = fmaxf(m1, e[j + 1]);
                m2 = fmaxf(m2, e[j + 2]); m3 = fmaxf(m3, e[j + 3]);
            }
            float m = fmaxf(fmaxf(m0, m1), fmaxf(m2, m3));
            float s0 = 0.f, s1 = 0.f, s2 = 0.f, s3 = 0.f;
#pragma unroll
            for (int j = 0; j < 32; j += 4) {
                e[j]     = __expf(e[j] - m);     s0 += e[j];
                e[j + 1] = __expf(e[j + 1] - m); s1 += e[j + 1];
                e[j + 2] = __expf(e[j + 2] - m); s2 += e[j + 2];
                e[j + 3] = __expf(e[j + 3] - m); s3 += e[j + 3];
            }
            float inv = __fdividef(1.0f, (s0 + s1) + (s2 + s3));
#pragma unroll
            for (int jj = 0; jj < 8; ++jj)
                *(float4*)&xb[AS(warp, lane, 4 * jj)] =
                    make_float4(tf32r(e[4 * jj] * inv), tf32r(e[4 * jj + 1] * inv),
                                tf32r(e[4 * jj + 2] * inv), tf32r(e[4 * jj + 3] * inv));
        }
        __syncthreads();

        // Phase C: out = attn_h @ h_h via tf32 MMA (per-head 32x32x32),
        // ELU epilogue. Layer 0 stores tf32-rounded (feeds next MMA),
        // layer 1 stores exact fp32 (feeds pooling).
        {
            const int n0 = warp * 32;
            float acc[2][4][4];
#pragma unroll
            for (int mt = 0; mt < 2; ++mt)
#pragma unroll
                for (int nt = 0; nt < 4; ++nt)
#pragma unroll
                    for (int r = 0; r < 4; ++r) acc[mt][nt][r] = 0.f;

#pragma unroll
            for (int kt = 0; kt < 4; ++kt) {
                const int k0 = kt * 8;
                uint32_t a[2][4];
#pragma unroll
                for (int mt = 0; mt < 2; ++mt) {
                    const int r0 = mt * 16 + gID;
                    a[mt][0] = __float_as_uint(xb[AS(warp, r0,     k0 + tig)]);
                    a[mt][1] = __float_as_uint(xb[AS(warp, r0 + 8, k0 + tig)]);
                    a[mt][2] = __float_as_uint(xb[AS(warp, r0,     k0 + tig + 4)]);
                    a[mt][3] = __float_as_uint(xb[AS(warp, r0 + 8, k0 + tig + 4)]);
                }
#pragma unroll
                for (int nt = 0; nt < 4; ++nt) {
                    const int n = n0 + nt * 8 + gID;
                    uint32_t b0 = __float_as_uint(hb[XS(k0 + tig,     n)]);
                    uint32_t b1 = __float_as_uint(hb[XS(k0 + tig + 4, n)]);
                    mma_tf32(acc[0][nt], a[0], b0, b1);
                    mma_tf32(acc[1][nt], a[1], b0, b1);
                }
            }
            __syncwarp();
#pragma unroll
            for (int mt = 0; mt < 2; ++mt)
#pragma unroll
                for (int nt = 0; nt < 4; ++nt) {
                    const int r = mt * 16 + gID;
                    const int c = n0 + nt * 8 + 2 * tig;
                    float o0 = acc[mt][nt][0], o1 = acc[mt][nt][1];
                    float o2 = acc[mt][nt][2], o3 = acc[mt][nt][3];
                    o0 = (o0 > 0.f) ? o0 : (__expf(o0) - 1.0f);
                    o1 = (o1 > 0.f) ? o1 : (__expf(o1) - 1.0f);
                    o2 = (o2 > 0.f) ? o2 : (__expf(o2) - 1.0f);
                    o3 = (o3 > 0.f) ? o3 : (__expf(o3) - 1.0f);
                    if (l == 0) {
                        o0 = tf32r(o0); o1 = tf32r(o1);
                        o2 = tf32r(o2); o3 = tf32r(o3);
                    }
                    *(float2*)&hb[XS(r, c)]     = make_float2(o0, o1);
                    *(float2*)&hb[XS(r + 8, c)] = make_float2(o2, o3);
                }
        }
        __syncthreads();

        // swap roles: new x is in hb
        float* tmp = xb; xb = hb; hb = tmp;
    }

    // ---- masked mean pooling (final x is in xb, exact fp32) ----
    {
        float acc = 0.f;
#pragma unroll
        for (int i = 0; i < NTOK; ++i)
            acc = fmaf(s_alive[i], xb[XS(i, t)], acc);
        out[(size_t)b * EDIM + t] = acc * s_inv;
    }
}

extern "C" void kernel_launch(void* const* d_in, const int* in_sizes, int n_in,
                              void* d_out, int out_size) {
    const float* obs = (const float*)d_in[0];
    const float* Wv  = (const float*)d_in[1];
    const float* bv  = (const float*)d_in[2];
    const float* Wp  = (const float*)d_in[3];
    const float* bp  = (const float*)d_in[4];
    const float* w0  = (const float*)d_in[5];
    const float* as0 = (const float*)d_in[6];
    const float* ad0 = (const float*)d_in[7];
    const float* w1  = (const float*)d_in[8];
    const float* as1 = (const float*)d_in[9];
    const float* ad1 = (const float*)d_in[10];
    float* out = (float*)d_out;

    int B = in_sizes[0] / OBSD;

    size_t shmem = 8192 * sizeof(float);   // 32 KB
    cudaFuncSetAttribute(gnn_kernel, cudaFuncAttributeMaxDynamicSharedMemorySize, (int)shmem);

    prep_kernel<<<(2 * EDIM * 136 + 255) / 256, 256>>>(w0, as0, ad0, w1, as1, ad1);
    gnn_kernel<<<B, 128, shmem>>>(obs, Wv, bv, Wp, bp, out);
}

// round 9
// speedup vs baseline: 3.5708x; 1.0461x over previous
#include <cuda_runtime.h>
#include <cstdint>

#define N_VEH 16
#define N_PED 16
#define NTOK  32
#define DVEH  40
#define DPED  24
#define EDIM  128
#define NHEAD 4
#define OBSD  1056   // 16*40 + 16*24 + 32

// Packed tf32 weights: g_wtp[l][kt][n][tig] = (w[kt*8+tig][n], w[kt*8+tig+4][n])
__device__ uint2 g_wtp[2][16][EDIM][4];
// Packed folded-alpha weights: [l][kt][j][tig], j: 0-3 src head j, 4-7 dst head j-4
__device__ uint2 g_wtAp[2][16][8][4];

__device__ __forceinline__ uint32_t f2tf32(float f) {
    uint32_t r;
    asm("cvt.rna.tf32.f32 %0, %1;" : "=r"(r) : "f"(f));
    return r;
}
__device__ __forceinline__ float tf32r(float f) {
    return __uint_as_float(f2tf32(f));
}

__device__ __forceinline__ void mma_tf32(float* c, const uint32_t* a,
                                         uint32_t b0, uint32_t b1) {
    asm("mma.sync.aligned.m16n8k8.row.col.f32.tf32.tf32.f32 "
        "{%0,%1,%2,%3}, {%4,%5,%6,%7}, {%8,%9}, {%0,%1,%2,%3};"
        : "+f"(c[0]), "+f"(c[1]), "+f"(c[2]), "+f"(c[3])
        : "r"(a[0]), "r"(a[1]), "r"(a[2]), "r"(a[3]), "r"(b0), "r"(b1));
}

// ---- fragment-paired SMEM layouts (all bijective on 32x128 = 4096 floats) ----
// PL (x matrices): pair (r, c) with (r, c+4) adjacent; bank-XOR on pair index.
__device__ __forceinline__ int plOff(int r, int c) {
    int p   = ((c >> 3) << 2) | (c & 3);     // pair index 0..63
    int hi  = (c >> 2) & 1;
    int sig = ((r & 3) << 2) | ((r >> 2) & 3);
    return (r << 7) + (((p ^ sig)) << 1) + hi;
}
// QL (h matrices): pair (r, c) with (r+4, c) adjacent.
__device__ __forceinline__ int qlOff(int r, int c) {
    int rr = ((r >> 3) << 2) | (r & 3);      // row-pair index 0..15
    int hi = (r >> 2) & 1;
    return (rr << 8) + ((c ^ ((rr & 3) << 2)) << 1) + hi;
}
// AL (attn, per head 32x32): pair (i, j) with (i, j+4) adjacent.
__device__ __forceinline__ int alOff(int h, int i, int p /*pair 0..15*/) {
    int sig = ((i & 3) << 2) | ((i >> 2) & 3);
    return (h << 10) + (i << 5) + ((p ^ sig) << 1);
}

// Fused prep: pack main weights + folded alpha weights as tf32 uint2 pairs.
__global__ void prep_kernel(const float* __restrict__ w0,
                            const float* __restrict__ as0, const float* __restrict__ ad0,
                            const float* __restrict__ w1,
                            const float* __restrict__ as1, const float* __restrict__ ad1) {
    int idx = blockIdx.x * blockDim.x + threadIdx.x;
    if (idx < 2 * 16 * EDIM * 4) {
        int l   = idx >> 13;
        int rem = idx & 8191;
        int kt  = rem >> 9;
        int n   = (rem >> 2) & 127;
        int tig = rem & 3;
        const float* w = l ? w1 : w0;
        g_wtp[l][kt][n][tig] =
            make_uint2(f2tf32(w[(kt * 8 + tig) * EDIM + n]),
                       f2tf32(w[(kt * 8 + tig + 4) * EDIM + n]));
    } else if (idx < 2 * 16 * EDIM * 4 + 2 * 16 * 8 * 4) {
        int i2  = idx - 2 * 16 * EDIM * 4;   // [0, 1024)
        int l   = i2 >> 9;
        int kt  = (i2 >> 5) & 15;
        int j   = (i2 >> 2) & 7;
        int tig = i2 & 3;
        const float* w = l ? w1 : w0;
        int h = j & 3;
        const float* a = (j < 4) ? (l ? as1 : as0) : (l ? ad1 : ad0);
        float s0 = 0.f, s1 = 0.f;
#pragma unroll
        for (int d = 0; d < 32; ++d) {
            float av = a[h * 32 + d];
            s0 = fmaf(w[(kt * 8 + tig) * EDIM + h * 32 + d],     av, s0);
            s1 = fmaf(w[(kt * 8 + tig + 4) * EDIM + h * 32 + d], av, s1);
        }
        g_wtAp[l][kt][j][tig] = make_uint2(f2tf32(s0), f2tf32(s1));
    }
}

__global__ __launch_bounds__(128, 6) void gnn_kernel(
    const float* __restrict__ obs,
    const float* __restrict__ Wv, const float* __restrict__ bv,
    const float* __restrict__ Wp, const float* __restrict__ bp,
    float* __restrict__ out)
{
    const int b    = blockIdx.x;
    const int t    = threadIdx.x;
    const int lane = t & 31;
    const int warp = t >> 5;
    const int gID  = lane >> 2;
    const int tig  = lane & 3;
    // sig for rows mt*16+gID (same for mt=0,1); rows +8 use sig^2.
    const int sigr = ((gID & 3) << 2) | (gID >> 2);

    extern __shared__ float smem[];
    float* bufP = smem;
    float* bufQ = smem + 4096;

    __shared__ float s_as[NTOK][NHEAD];
    __shared__ float s_adt[NHEAD][NTOK];
    __shared__ float s_bias[NTOK];
    __shared__ float s_alive[NTOK];
    __shared__ float s_inv;

    // ---- stage observation row into bufQ ----
    {
        const float4* src = (const float4*)(obs + (size_t)b * OBSD);
        float4* dst = (float4*)bufQ;
        for (int i = t; i < OBSD / 4; i += 128) dst[i] = src[i];
    }
    __syncthreads();
    const float* s_obs = bufQ;

    // ---- alive mask (warp 0) ----
    if (warp == 0) {
        float raw = s_obs[N_VEH * DVEH + N_PED * DPED + lane];
        int a = (raw >= 0.5f) ? 1 : 0;
        unsigned m = __ballot_sync(0xffffffffu, a);
        int cnt = __popc(m);
        if (cnt == 0) { a = 1; cnt = NTOK; }
        s_alive[lane] = (float)a;
        s_bias[lane]  = a ? 0.f : -1e30f;
        if (lane == 0) s_inv = 1.0f / (float)cnt;
    }

    // ---- token embeddings into bufP (PL layout, tf32-rounded) ----
    {
        float acc[16];
        float bvt = bv[t];
#pragma unroll
        for (int n = 0; n < 16; ++n) acc[n] = bvt;
        for (int d = 0; d < DVEH; d += 4) {
            float wq0 = Wv[(d + 0) * EDIM + t];
            float wq1 = Wv[(d + 1) * EDIM + t];
            float wq2 = Wv[(d + 2) * EDIM + t];
            float wq3 = Wv[(d + 3) * EDIM + t];
#pragma unroll
            for (int n = 0; n < 16; ++n) {
                float4 ov = *(const float4*)&s_obs[n * DVEH + d];
                acc[n] = fmaf(ov.x, wq0, fmaf(ov.y, wq1,
                         fmaf(ov.z, wq2, fmaf(ov.w, wq3, acc[n]))));
            }
        }
        float accp[16];
        float bpt = bp[t];
#pragma unroll
        for (int n = 0; n < 16; ++n) accp[n] = bpt;
        for (int d = 0; d < DPED; d += 4) {
            float wq0 = Wp[(d + 0) * EDIM + t];
            float wq1 = Wp[(d + 1) * EDIM + t];
            float wq2 = Wp[(d + 2) * EDIM + t];
            float wq3 = Wp[(d + 3) * EDIM + t];
#pragma unroll
            for (int n = 0; n < 16; ++n) {
                float4 ov = *(const float4*)&s_obs[N_VEH * DVEH + n * DPED + d];
                accp[n] = fmaf(ov.x, wq0, fmaf(ov.y, wq1,
                          fmaf(ov.z, wq2, fmaf(ov.w, wq3, accp[n]))));
            }
        }
        __syncthreads();   // obs fully consumed before overwriting buffers
#pragma unroll
        for (int n = 0; n < 16; ++n) bufP[plOff(n, t)] = tf32r(acc[n]);
#pragma unroll
        for (int n = 0; n < 16; ++n) bufP[plOff(16 + n, t)] = tf32r(accp[n]);
    }
    __syncthreads();

    float* xb = bufP;   // current x (PL)
    float* hb = bufQ;   // h target (QL) / next x target

    // ---- two GAT layers ----
#pragma unroll
    for (int l = 0; l < 2; ++l) {
        // Phase A1: h = x @ w via tf32 MMA (A from PL via LDS.64, B packed LDG.64).
        {
            const int n0w = warp * 32;
            float acc[2][4][4];
            float accA[2][4];
#pragma unroll
            for (int mt = 0; mt < 2; ++mt) {
#pragma unroll
                for (int nt = 0; nt < 4; ++nt)
#pragma unroll
                    for (int r = 0; r < 4; ++r) acc[mt][nt][r] = 0.f;
#pragma unroll
                for (int r = 0; r < 4; ++r) accA[mt][r] = 0.f;
            }

#pragma unroll 4
            for (int kt = 0; kt < 16; ++kt) {
                const int pA = kt * 4 + tig;
                uint32_t a[2][4];
#pragma unroll
                for (int mt = 0; mt < 2; ++mt) {
                    const int r0 = mt * 16 + gID;
                    float2 v0 = *(const float2*)&xb[(r0 << 7) + ((pA ^ sigr) << 1)];
                    float2 v1 = *(const float2*)&xb[((r0 + 8) << 7) + ((pA ^ (sigr ^ 2)) << 1)];
                    a[mt][0] = __float_as_uint(v0.x);
                    a[mt][1] = __float_as_uint(v1.x);
                    a[mt][2] = __float_as_uint(v0.y);
                    a[mt][3] = __float_as_uint(v1.y);
                }
#pragma unroll
                for (int nt = 0; nt < 4; ++nt) {
                    const int n = n0w + nt * 8 + gID;
                    uint2 bv = g_wtp[l][kt][n][tig];
                    mma_tf32(acc[0][nt], a[0], bv.x, bv.y);
                    mma_tf32(acc[1][nt], a[1], bv.x, bv.y);
                }
                if (warp == 0) {
                    uint2 bA = g_wtAp[l][kt][gID][tig];
                    mma_tf32(accA[0], a[0], bA.x, bA.y);
                    mma_tf32(accA[1], a[1], bA.x, bA.y);
                }
            }
            // epilogue: h into QL (scalar stores)
#pragma unroll
            for (int mt = 0; mt < 2; ++mt)
#pragma unroll
                for (int nt = 0; nt < 4; ++nt) {
                    const int r = mt * 16 + gID;
                    const int c = n0w + nt * 8 + 2 * tig;
                    hb[qlOff(r,     c)]     = tf32r(acc[mt][nt][0]);
                    hb[qlOff(r,     c + 1)] = tf32r(acc[mt][nt][1]);
                    hb[qlOff(r + 8, c)]     = tf32r(acc[mt][nt][2]);
                    hb[qlOff(r + 8, c + 1)] = tf32r(acc[mt][nt][3]);
                }
            if (warp == 0) {
#pragma unroll
                for (int mt = 0; mt < 2; ++mt) {
                    const int r = mt * 16 + gID;
#pragma unroll
                    for (int q = 0; q < 4; ++q) {
                        int row = (q < 2) ? r : (r + 8);
                        int col = 2 * tig + (q & 1);
                        float v = accA[mt][q];
                        if (col < 4) s_as[row][col] = v;
                        else         s_adt[col - 4][row] = v;
                    }
                }
            }
        }
        __syncthreads();   // x consumed; attn may overwrite xb

        // Phase B: shuffle-free softmax. warp = head, lane = dst row i.
        {
            const int siga = ((lane & 3) << 2) | ((lane >> 2) & 3);
            float as_i = s_as[lane][warp];
            float e[32];
#pragma unroll
            for (int jj = 0; jj < 8; ++jj) {
                float4 ad4 = *(const float4*)&s_adt[warp][4 * jj];
                float4 b4  = *(const float4*)&s_bias[4 * jj];
                float v;
                v = as_i + ad4.x; e[4 * jj + 0] = ((v > 0.f) ? v : 0.2f * v) + b4.x;
                v = as_i + ad4.y; e[4 * jj + 1] = ((v > 0.f) ? v : 0.2f * v) + b4.y;
                v = as_i + ad4.z; e[4 * jj + 2] = ((v > 0.f) ? v : 0.2f * v) + b4.z;
                v = as_i + ad4.w; e[4 * jj + 3] = ((v > 0.f) ? v : 0.2f * v) + b4.w;
            }
            float m0 = e[0], m1 = e[1], m2 = e[2], m3 = e[3];
#pragma unroll
            for (int j = 4; j < 32; j += 4) {
                m0 = fmaxf(m0, e[j]);     m1 = fmaxf(m1, e[j + 1]);
                m2 = fmaxf(m2, e[j + 2]); m3 = fmaxf(m3, e[j + 3]);
            }
            float m = fmaxf(fmaxf(m0, m1), fmaxf(m2, m3));
            float s0 = 0.f, s1 = 0.f, s2 = 0.f, s3 = 0.f;
#pragma unroll
            for (int j = 0; j < 32; j += 4) {
                e[j]     = __expf(e[j] - m);     s0 += e[j];
                e[j + 1] = __expf(e[j + 1] - m); s1 += e[j + 1];
                e[j + 2] = __expf(e[j + 2] - m); s2 += e[j + 2];
                e[j + 3] = __expf(e[j + 3] - m); s3 += e[j + 3];
            }
            float inv = __fdividef(1.0f, (s0 + s1) + (s2 + s3));
            // write AL pairs (j, j+4) as STS.64
#pragma unroll
            for (int p = 0; p < 16; ++p) {
                int j = ((p >> 2) << 3) | (p & 3);
                *(float2*)&xb[(warp << 10) + (lane << 5) + ((p ^ siga) << 1)] =
                    make_float2(tf32r(e[j] * inv), tf32r(e[j + 4] * inv));
            }
        }
        __syncthreads();

        // Phase C: out = attn_h @ h_h via tf32 MMA (A from AL, B from QL, all LDS.64).
        {
            const int n0 = warp * 32;
            float acc[2][4][4];
#pragma unroll
            for (int mt = 0; mt < 2; ++mt)
#pragma unroll
                for (int nt = 0; nt < 4; ++nt)
#pragma unroll
                    for (int r = 0; r < 4; ++r) acc[mt][nt][r] = 0.f;

#pragma unroll
            for (int kt = 0; kt < 4; ++kt) {
                const int pC = kt * 4 + tig;
                uint32_t a[2][4];
#pragma unroll
                for (int mt = 0; mt < 2; ++mt) {
                    const int r0 = mt * 16 + gID;
                    float2 v0 = *(const float2*)&xb[(warp << 10) + (r0 << 5) + ((pC ^ sigr) << 1)];
                    float2 v1 = *(const float2*)&xb[(warp << 10) + ((r0 + 8) << 5) + ((pC ^ (sigr ^ 2)) << 1)];
                    a[mt][0] = __float_as_uint(v0.x);
                    a[mt][1] = __float_as_uint(v1.x);
                    a[mt][2] = __float_as_uint(v0.y);
                    a[mt][3] = __float_as_uint(v1.y);
                }
#pragma unroll
                for (int nt = 0; nt < 4; ++nt) {
                    const int n = n0 + nt * 8 + gID;
                    float2 bv = *(const float2*)&hb[(pC << 8) + ((n ^ (tig << 2)) << 1)];
                    mma_tf32(acc[0][nt], a[0], __float_as_uint(bv.x), __float_as_uint(bv.y));
                    mma_tf32(acc[1][nt], a[1], __float_as_uint(bv.x), __float_as_uint(bv.y));
                }
            }
            __syncwarp();
            // epilogue: ELU, write x' into hb in PL layout (own col slice only)
#pragma unroll
            for (int mt = 0; mt < 2; ++mt)
#pragma unroll
                for (int nt = 0; nt < 4; ++nt) {
                    const int r = mt * 16 + gID;
                    const int c = n0 + nt * 8 + 2 * tig;
                    float o0 = acc[mt][nt][0], o1 = acc[mt][nt][1];
                    float o2 = acc[mt][nt][2], o3 = acc[mt][nt][3];
                    o0 = (o0 > 0.f) ? o0 : (__expf(o0) - 1.0f);
                    o1 = (o1 > 0.f) ? o1 : (__expf(o1) - 1.0f);
                    o2 = (o2 > 0.f) ? o2 : (__expf(o2) - 1.0f);
                    o3 = (o3 > 0.f) ? o3 : (__expf(o3) - 1.0f);
                    if (l == 0) {
                        o0 = tf32r(o0); o1 = tf32r(o1);
                        o2 = tf32r(o2); o3 = tf32r(o3);
                    }
                    hb[plOff(r,     c)]     = o0;
                    hb[plOff(r,     c + 1)] = o1;
                    hb[plOff(r + 8, c)]     = o2;
                    hb[plOff(r + 8, c + 1)] = o3;
                }
        }
        __syncthreads();

        // swap roles: new x is in hb
        float* tmp = xb; xb = hb; hb = tmp;
    }

    // ---- masked mean pooling (final x in xb, PL, exact fp32) ----
    {
        float acc = 0.f;
#pragma unroll
        for (int i = 0; i < NTOK; ++i)
            acc = fmaf(s_alive[i], xb[plOff(i, t)], acc);
        out[(size_t)b * EDIM + t] = acc * s_inv;
    }
}

extern "C" void kernel_launch(void* const* d_in, const int* in_sizes, int n_in,
                              void* d_out, int out_size) {
    const float* obs = (const float*)d_in[0];
    const float* Wv  = (const float*)d_in[1];
    const float* bv  = (const float*)d_in[2];
    const float* Wp  = (const float*)d_in[3];
    const float* bp  = (const float*)d_in[4];
    const float* w0  = (const float*)d_in[5];
    const float* as0 = (const float*)d_in[6];
    const float* ad0 = (const float*)d_in[7];
    const float* w1  = (const float*)d_in[8];
    const float* as1 = (const float*)d_in[9];
    const float* ad1 = (const float*)d_in[10];
    float* out = (float*)d_out;

    int B = in_sizes[0] / OBSD;

    size_t shmem = 8192 * sizeof(float);   // 32 KB
    cudaFuncSetAttribute(gnn_kernel, cudaFuncAttributeMaxDynamicSharedMemorySize, (int)shmem);

    int prep_total = 2 * 16 * EDIM * 4 + 2 * 16 * 8 * 4;   // 17408
    prep_kernel<<<(prep_total + 255) / 256, 256>>>(w0, as0, ad0, w1, as1, ad1);
    gnn_kernel<<<B, 128, shmem>>>(obs, Wv, bv, Wp, bp, out);
}

// round 10
// speedup vs baseline: 4.1811x; 1.1709x over previous
#include <cuda_runtime.h>
#include <cstdint>

#define N_VEH 16
#define N_PED 16
#define NTOK  32
#define DVEH  40
#define DPED  24
#define EDIM  128
#define NHEAD 4
#define OBSD  1056   // 16*40 + 16*24 + 32

// Packed tf32 weights: g_wtp[l][kt][n][tig] = (w[kt*8+tig][n], w[kt*8+tig+4][n])
__device__ uint2 g_wtp[2][16][EDIM][4];
// Packed folded-alpha weights: [l][kt][j][tig], j: 0-3 src head j, 4-7 dst head j-4
__device__ uint2 g_wtAp[2][16][8][4];
// Packed embedding weights (tf32 pairs): Wv 5 k-tiles, Wp 3 k-tiles.
__device__ uint2 g_wvp[5][EDIM][4];
__device__ uint2 g_wpp[3][EDIM][4];

__device__ __forceinline__ uint32_t f2tf32(float f) {
    uint32_t r;
    asm("cvt.rna.tf32.f32 %0, %1;" : "=r"(r) : "f"(f));
    return r;
}
__device__ __forceinline__ float tf32r(float f) {
    return __uint_as_float(f2tf32(f));
}

__device__ __forceinline__ void mma_tf32(float* c, const uint32_t* a,
                                         uint32_t b0, uint32_t b1) {
    asm("mma.sync.aligned.m16n8k8.row.col.f32.tf32.tf32.f32 "
        "{%0,%1,%2,%3}, {%4,%5,%6,%7}, {%8,%9}, {%0,%1,%2,%3};"
        : "+f"(c[0]), "+f"(c[1]), "+f"(c[2]), "+f"(c[3])
        : "r"(a[0]), "r"(a[1]), "r"(a[2]), "r"(a[3]), "r"(b0), "r"(b1));
}

// ---- fragment-paired SMEM layouts ----
// PL (x matrices): pair (r, c) with (r, c+4) adjacent; bank-XOR on pair index.
__device__ __forceinline__ int plOff(int r, int c) {
    int p   = ((c >> 3) << 2) | (c & 3);     // pair index 0..63
    int hi  = (c >> 2) & 1;
    int sig = ((r & 3) << 2) | ((r >> 2) & 3);
    return (r << 7) + (((p ^ sig)) << 1) + hi;
}
// QL (h matrices): pair (r, c) with (r+4, c) adjacent.
__device__ __forceinline__ int qlOff(int r, int c) {
    int rr = ((r >> 3) << 2) | (r & 3);      // row-pair index 0..15
    int hi = (r >> 2) & 1;
    return (rr << 8) + ((c ^ ((rr & 3) << 2)) << 1) + hi;
}

// Fused prep: pack main, alpha, and embedding weights as tf32 uint2 pairs.
__global__ void prep_kernel(const float* __restrict__ w0,
                            const float* __restrict__ as0, const float* __restrict__ ad0,
                            const float* __restrict__ w1,
                            const float* __restrict__ as1, const float* __restrict__ ad1,
                            const float* __restrict__ Wv, const float* __restrict__ Wp) {
    int idx = blockIdx.x * blockDim.x + threadIdx.x;
    if (idx < 16384) {                       // main weights: 2*16*128*4
        int l   = idx >> 13;
        int rem = idx & 8191;
        int kt  = rem >> 9;
        int n   = (rem >> 2) & 127;
        int tig = rem & 3;
        const float* w = l ? w1 : w0;
        g_wtp[l][kt][n][tig] =
            make_uint2(f2tf32(w[(kt * 8 + tig) * EDIM + n]),
                       f2tf32(w[(kt * 8 + tig + 4) * EDIM + n]));
    } else if (idx < 16384 + 1024) {         // folded alpha: 2*16*8*4
        int i2  = idx - 16384;
        int l   = i2 >> 9;
        int kt  = (i2 >> 5) & 15;
        int j   = (i2 >> 2) & 7;
        int tig = i2 & 3;
        const float* w = l ? w1 : w0;
        int h = j & 3;
        const float* a = (j < 4) ? (l ? as1 : as0) : (l ? ad1 : ad0);
        float s0 = 0.f, s1 = 0.f;
#pragma unroll
        for (int d = 0; d < 32; ++d) {
            float av = a[h * 32 + d];
            s0 = fmaf(w[(kt * 8 + tig) * EDIM + h * 32 + d],     av, s0);
            s1 = fmaf(w[(kt * 8 + tig + 4) * EDIM + h * 32 + d], av, s1);
        }
        g_wtAp[l][kt][j][tig] = make_uint2(f2tf32(s0), f2tf32(s1));
    } else if (idx < 16384 + 1024 + 2560) {  // Wv: 5*128*4
        int i2  = idx - 16384 - 1024;
        int kt  = i2 >> 9;
        int n   = (i2 >> 2) & 127;
        int tig = i2 & 3;
        g_wvp[kt][n][tig] =
            make_uint2(f2tf32(Wv[(kt * 8 + tig) * EDIM + n]),
                       f2tf32(Wv[(kt * 8 + tig + 4) * EDIM + n]));
    } else if (idx < 16384 + 1024 + 2560 + 1536) {   // Wp: 3*128*4
        int i2  = idx - 16384 - 1024 - 2560;
        int kt  = i2 >> 9;
        int n   = (i2 >> 2) & 127;
        int tig = i2 & 3;
        g_wpp[kt][n][tig] =
            make_uint2(f2tf32(Wp[(kt * 8 + tig) * EDIM + n]),
                       f2tf32(Wp[(kt * 8 + tig + 4) * EDIM + n]));
    }
}

__global__ __launch_bounds__(128, 6) void gnn_kernel(
    const float* __restrict__ obs,
    const float* __restrict__ bv, const float* __restrict__ bp,
    float* __restrict__ out)
{
    const int b    = blockIdx.x;
    const int t    = threadIdx.x;
    const int lane = t & 31;
    const int warp = t >> 5;
    const int gID  = lane >> 2;
    const int tig  = lane & 3;
    // sig for rows mt*16+gID (same for mt=0,1); rows +8 use sig^2.
    const int sigr = ((gID & 3) << 2) | (gID >> 2);

    extern __shared__ float smem[];
    float* bufP = smem;
    float* bufQ = smem + 4096;

    __shared__ float s_as[NTOK][NHEAD];
    __shared__ float s_adt[NHEAD][NTOK];
    __shared__ float s_bias[NTOK];
    __shared__ float s_alive[NTOK];
    __shared__ float s_inv;

    // ---- stage observation row into bufQ ----
    {
        const float4* src = (const float4*)(obs + (size_t)b * OBSD);
        float4* dst = (float4*)bufQ;
        for (int i = t; i < OBSD / 4; i += 128) dst[i] = src[i];
    }
    __syncthreads();
    const float* s_obs = bufQ;

    // ---- alive mask (warp 0) ----
    if (warp == 0) {
        float raw = s_obs[N_VEH * DVEH + N_PED * DPED + lane];
        int a = (raw >= 0.5f) ? 1 : 0;
        unsigned m = __ballot_sync(0xffffffffu, a);
        int cnt = __popc(m);
        if (cnt == 0) { a = 1; cnt = NTOK; }
        s_alive[lane] = (float)a;
        s_bias[lane]  = a ? 0.f : -1e30f;
        if (lane == 0) s_inv = 1.0f / (float)cnt;
    }

    // ---- token embeddings via tf32 MMA -> bufP (PL layout) ----
    // veh tile: rows 0-15 (tokens), ped tile: rows 16-31. Bias in acc init.
    {
        const int n0w = warp * 32;
        float accV[4][4], accP[4][4];
#pragma unroll
        for (int nt = 0; nt < 4; ++nt) {
            const int c = n0w + nt * 8 + 2 * tig;
            float2 b2 = *(const float2*)&bv[c];
            accV[nt][0] = b2.x; accV[nt][1] = b2.y;
            accV[nt][2] = b2.x; accV[nt][3] = b2.y;
            float2 p2 = *(const float2*)&bp[c];
            accP[nt][0] = p2.x; accP[nt][1] = p2.y;
            accP[nt][2] = p2.x; accP[nt][3] = p2.y;
        }
        // vehicle: k = 0..39, 5 k-tiles
#pragma unroll
        for (int kt = 0; kt < 5; ++kt) {
            const int k = kt * 8 + tig;
            uint32_t a[4];
            a[0] = f2tf32(s_obs[gID * DVEH + k]);
            a[1] = f2tf32(s_obs[(gID + 8) * DVEH + k]);
            a[2] = f2tf32(s_obs[gID * DVEH + k + 4]);
            a[3] = f2tf32(s_obs[(gID + 8) * DVEH + k + 4]);
#pragma unroll
            for (int nt = 0; nt < 4; ++nt) {
                uint2 bw = g_wvp[kt][n0w + nt * 8 + gID][tig];
                mma_tf32(accV[nt], a, bw.x, bw.y);
            }
        }
        // pedestrian: k = 0..23, 3 k-tiles, tokens 16-31
#pragma unroll
        for (int kt = 0; kt < 3; ++kt) {
            const int k = kt * 8 + tig;
            const int base = N_VEH * DVEH;
            uint32_t a[4];
            a[0] = f2tf32(s_obs[base + gID * DPED + k]);
            a[1] = f2tf32(s_obs[base + (gID + 8) * DPED + k]);
            a[2] = f2tf32(s_obs[base + gID * DPED + k + 4]);
            a[3] = f2tf32(s_obs[base + (gID + 8) * DPED + k + 4]);
#pragma unroll
            for (int nt = 0; nt < 4; ++nt) {
                uint2 bw = g_wpp[kt][n0w + nt * 8 + gID][tig];
                mma_tf32(accP[nt], a, bw.x, bw.y);
            }
        }
        // epilogue: write x into bufP (PL), tf32-rounded
#pragma unroll
        for (int nt = 0; nt < 4; ++nt) {
            const int c = n0w + nt * 8 + 2 * tig;
            bufP[plOff(gID,      c)]     = tf32r(accV[nt][0]);
            bufP[plOff(gID,      c + 1)] = tf32r(accV[nt][1]);
            bufP[plOff(gID + 8,  c)]     = tf32r(accV[nt][2]);
            bufP[plOff(gID + 8,  c + 1)] = tf32r(accV[nt][3]);
            bufP[plOff(16 + gID,     c)]     = tf32r(accP[nt][0]);
            bufP[plOff(16 + gID,     c + 1)] = tf32r(accP[nt][1]);
            bufP[plOff(16 + gID + 8, c)]     = tf32r(accP[nt][2]);
            bufP[plOff(16 + gID + 8, c + 1)] = tf32r(accP[nt][3]);
        }
    }
    __syncthreads();

    float* xb = bufP;   // current x (PL)
    float* hb = bufQ;   // h target (QL) / next x target

    // ---- two GAT layers ----
#pragma unroll
    for (int l = 0; l < 2; ++l) {
        // Phase A1: h = x @ w via tf32 MMA (A from PL via LDS.64, B packed LDG.64).
        {
            const int n0w = warp * 32;
            float acc[2][4][4];
            float accA[2][4];
#pragma unroll
            for (int mt = 0; mt < 2; ++mt) {
#pragma unroll
                for (int nt = 0; nt < 4; ++nt)
#pragma unroll
                    for (int r = 0; r < 4; ++r) acc[mt][nt][r] = 0.f;
#pragma unroll
                for (int r = 0; r < 4; ++r) accA[mt][r] = 0.f;
            }

#pragma unroll 4
            for (int kt = 0; kt < 16; ++kt) {
                const int pA = kt * 4 + tig;
                uint32_t a[2][4];
#pragma unroll
                for (int mt = 0; mt < 2; ++mt) {
                    const int r0 = mt * 16 + gID;
                    float2 v0 = *(const float2*)&xb[(r0 << 7) + ((pA ^ sigr) << 1)];
                    float2 v1 = *(const float2*)&xb[((r0 + 8) << 7) + ((pA ^ (sigr ^ 2)) << 1)];
                    a[mt][0] = __float_as_uint(v0.x);
                    a[mt][1] = __float_as_uint(v1.x);
                    a[mt][2] = __float_as_uint(v0.y);
                    a[mt][3] = __float_as_uint(v1.y);
                }
#pragma unroll
                for (int nt = 0; nt < 4; ++nt) {
                    const int n = n0w + nt * 8 + gID;
                    uint2 bw = g_wtp[l][kt][n][tig];
                    mma_tf32(acc[0][nt], a[0], bw.x, bw.y);
                    mma_tf32(acc[1][nt], a[1], bw.x, bw.y);
                }
                if (warp == 0) {
                    uint2 bA = g_wtAp[l][kt][gID][tig];
                    mma_tf32(accA[0], a[0], bA.x, bA.y);
                    mma_tf32(accA[1], a[1], bA.x, bA.y);
                }
            }
            // epilogue: h into QL (scalar stores)
#pragma unroll
            for (int mt = 0; mt < 2; ++mt)
#pragma unroll
                for (int nt = 0; nt < 4; ++nt) {
                    const int r = mt * 16 + gID;
                    const int c = n0w + nt * 8 + 2 * tig;
                    hb[qlOff(r,     c)]     = tf32r(acc[mt][nt][0]);
                    hb[qlOff(r,     c + 1)] = tf32r(acc[mt][nt][1]);
                    hb[qlOff(r + 8, c)]     = tf32r(acc[mt][nt][2]);
                    hb[qlOff(r + 8, c + 1)] = tf32r(acc[mt][nt][3]);
                }
            if (warp == 0) {
#pragma unroll
                for (int mt = 0; mt < 2; ++mt) {
                    const int r = mt * 16 + gID;
#pragma unroll
                    for (int q = 0; q < 4; ++q) {
                        int row = (q < 2) ? r : (r + 8);
                        int col = 2 * tig + (q & 1);
                        float v = accA[mt][q];
                        if (col < 4) s_as[row][col] = v;
                        else         s_adt[col - 4][row] = v;
                    }
                }
            }
        }
        __syncthreads();   // x consumed; attn may overwrite xb

        // Phase B: shuffle-free softmax. warp = head, lane = dst row i.
        {
            const int siga = ((lane & 3) << 2) | ((lane >> 2) & 3);
            float as_i = s_as[lane][warp];
            float e[32];
#pragma unroll
            for (int jj = 0; jj < 8; ++jj) {
                float4 ad4 = *(const float4*)&s_adt[warp][4 * jj];
                float4 b4  = *(const float4*)&s_bias[4 * jj];
                float v;
                v = as_i + ad4.x; e[4 * jj + 0] = ((v > 0.f) ? v : 0.2f * v) + b4.x;
                v = as_i + ad4.y; e[4 * jj + 1] = ((v > 0.f) ? v : 0.2f * v) + b4.y;
                v = as_i + ad4.z; e[4 * jj + 2] = ((v > 0.f) ? v : 0.2f * v) + b4.z;
                v = as_i + ad4.w; e[4 * jj + 3] = ((v > 0.f) ? v : 0.2f * v) + b4.w;
            }
            float m0 = e[0], m1 = e[1], m2 = e[2], m3 = e[3];
#pragma unroll
            for (int j = 4; j < 32; j += 4) {
                m0 = fmaxf(m0, e[j]);     m1 = fmaxf(m1, e[j + 1]);
                m2 = fmaxf(m2, e[j + 2]); m3 = fmaxf(m3, e[j + 3]);
            }
            float m = fmaxf(fmaxf(m0, m1), fmaxf(m2, m3));
            float s0 = 0.f, s1 = 0.f, s2 = 0.f, s3 = 0.f;
#pragma unroll
            for (int j = 0; j < 32; j += 4) {
                e[j]     = __expf(e[j] - m);     s0 += e[j];
                e[j + 1] = __expf(e[j + 1] - m); s1 += e[j + 1];
                e[j + 2] = __expf(e[j + 2] - m); s2 += e[j + 2];
                e[j + 3] = __expf(e[j + 3] - m); s3 += e[j + 3];
            }
            float inv = __fdividef(1.0f, (s0 + s1) + (s2 + s3));
            // write AL pairs (j, j+4) as STS.64
#pragma unroll
            for (int p = 0; p < 16; ++p) {
                int j = ((p >> 2) << 3) | (p & 3);
                *(float2*)&xb[(warp << 10) + (lane << 5) + ((p ^ siga) << 1)] =
                    make_float2(tf32r(e[j] * inv), tf32r(e[j + 4] * inv));
            }
        }
        __syncthreads();

        // Phase C: out = attn_h @ h_h via tf32 MMA (A from AL, B from QL, all LDS.64).
        {
            const int n0 = warp * 32;
            float acc[2][4][4];
#pragma unroll
            for (int mt = 0; mt < 2; ++mt)
#pragma unroll
                for (int nt = 0; nt < 4; ++nt)
#pragma unroll
                    for (int r = 0; r < 4; ++r) acc[mt][nt][r] = 0.f;

#pragma unroll
            for (int kt = 0; kt < 4; ++kt) {
                const int pC = kt * 4 + tig;
                uint32_t a[2][4];
#pragma unroll
                for (int mt = 0; mt < 2; ++mt) {
                    const int r0 = mt * 16 + gID;
                    float2 v0 = *(const float2*)&xb[(warp << 10) + (r0 << 5) + ((pC ^ sigr) << 1)];
                    float2 v1 = *(const float2*)&xb[(warp << 10) + ((r0 + 8) << 5) + ((pC ^ (sigr ^ 2)) << 1)];
                    a[mt][0] = __float_as_uint(v0.x);
                    a[mt][1] = __float_as_uint(v1.x);
                    a[mt][2] = __float_as_uint(v0.y);
                    a[mt][3] = __float_as_uint(v1.y);
                }
#pragma unroll
                for (int nt = 0; nt < 4; ++nt) {
                    const int n = n0 + nt * 8 + gID;
                    float2 bw = *(const float2*)&hb[(pC << 8) + ((n ^ (tig << 2)) << 1)];
                    mma_tf32(acc[0][nt], a[0], __float_as_uint(bw.x), __float_as_uint(bw.y));
                    mma_tf32(acc[1][nt], a[1], __float_as_uint(bw.x), __float_as_uint(bw.y));
                }
            }
            __syncwarp();
            // epilogue: ELU, write x' into hb in PL layout (own col slice only)
#pragma unroll
            for (int mt = 0; mt < 2; ++mt)
#pragma unroll
                for (int nt = 0; nt < 4; ++nt) {
                    const int r = mt * 16 + gID;
                    const int c = n0 + nt * 8 + 2 * tig;
                    float o0 = acc[mt][nt][0], o1 = acc[mt][nt][1];
                    float o2 = acc[mt][nt][2], o3 = acc[mt][nt][3];
                    o0 = (o0 > 0.f) ? o0 : (__expf(o0) - 1.0f);
                    o1 = (o1 > 0.f) ? o1 : (__expf(o1) - 1.0f);
                    o2 = (o2 > 0.f) ? o2 : (__expf(o2) - 1.0f);
                    o3 = (o3 > 0.f) ? o3 : (__expf(o3) - 1.0f);
                    if (l == 0) {
                        o0 = tf32r(o0); o1 = tf32r(o1);
                        o2 = tf32r(o2); o3 = tf32r(o3);
                    }
                    hb[plOff(r,     c)]     = o0;
                    hb[plOff(r,     c + 1)] = o1;
                    hb[plOff(r + 8, c)]     = o2;
                    hb[plOff(r + 8, c + 1)] = o3;
                }
        }
        __syncthreads();

        // swap roles: new x is in hb
        float* tmp = xb; xb = hb; hb = tmp;
    }

    // ---- masked mean pooling (final x in xb, PL, exact fp32) ----
    {
        float acc = 0.f;
#pragma unroll
        for (int i = 0; i < NTOK; ++i)
            acc = fmaf(s_alive[i], xb[plOff(i, t)], acc);
        out[(size_t)b * EDIM + t] = acc * s_inv;
    }
}

extern "C" void kernel_launch(void* const* d_in, const int* in_sizes, int n_in,
                              void* d_out, int out_size) {
    const float* obs = (const float*)d_in[0];
    const float* Wv  = (const float*)d_in[1];
    const float* bv  = (const float*)d_in[2];
    const float* Wp  = (const float*)d_in[3];
    const float* bp  = (const float*)d_in[4];
    const float* w0  = (const float*)d_in[5];
    const float* as0 = (const float*)d_in[6];
    const float* ad0 = (const float*)d_in[7];
    const float* w1  = (const float*)d_in[8];
    const float* as1 = (const float*)d_in[9];
    const float* ad1 = (const float*)d_in[10];
    float* out = (float*)d_out;

    int B = in_sizes[0] / OBSD;

    size_t shmem = 8192 * sizeof(float);   // 32 KB
    cudaFuncSetAttribute(gnn_kernel, cudaFuncAttributeMaxDynamicSharedMemorySize, (int)shmem);

    int prep_total = 16384 + 1024 + 2560 + 1536;   // 21504
    prep_kernel<<<(prep_total + 255) / 256, 256>>>(w0, as0, ad0, w1, as1, ad1, Wv, Wp);
    gnn_kernel<<<B, 128, shmem>>>(obs, bv, bp, out);
}